// round 12
// baseline (speedup 1.0000x reference)
#include <cuda_runtime.h>
#include <cuda_fp16.h>
#include <cstdint>

// ---------------- problem constants ----------------
#define NMAX   200000
#define CCH    64
#define KTAPS  9
#define TN     128          // rows per block (MMA M)
#define NTHR   128
#define LEAK   0.01f
#define EPS_BN 1e-5f
#define WSCALE 256.0f       // weight scaling (keeps fp16 lo-plane normal)
#define INV_WSCALE (1.0f / 256.0f)

// dynamic smem: 3 A stages x 16K (compute) / fp32 epilogue tile 34816B
#define STAGE_BYTES 16384
#define NSTAGE 3
#define DSM_BYTES (NSTAGE * STAGE_BYTES)
#define SC_STRIDE 68        // epilogue fp32 tile stride (floats)

// B fragment layout: halves per tap = 4q * (2wn*4c) chunks * 32 lanes * 8 = 8192
#define FRAG_TAP_HALVES   8192
#define FRAG_TENSOR_HALVES (KTAPS * FRAG_TAP_HALVES)   // 73728

// ---------------- scratch (no cudaMalloc allowed) ----------------
__device__ float g_bufB[(size_t)NMAX * CCH];
// fp16 feature rows: [row][64 fp16]; row nTotal = zero pad
__device__ __half g_fS[((size_t)NMAX + 1) * 64];
__device__ __half g_aS[((size_t)NMAX + 1) * 64];
__device__ __half g_wFrag[4 * FRAG_TENSOR_HALVES];   // B in per-lane MMA fragment layout
__device__ __half g_biasHi[4 * 64 * 16];             // [tensor][o*16 + tap], x256
__device__ __half g_biasLo[4 * 64 * 16];
__device__ float g_sums [4][CCH];
__device__ float g_sumsq[4][CCH];

// ---------------- helpers ----------------
__device__ __forceinline__ uint32_t smem_u32(const void* p) {
    uint32_t a;
    asm("{ .reg .u64 t; cvta.to.shared.u64 t, %1; cvt.u32.u64 %0, t; }" : "=r"(a) : "l"(p));
    return a;
}
__device__ __forceinline__ void ldsm4(uint32_t* r, uint32_t addr) {
    asm volatile("ldmatrix.sync.aligned.m8n8.x4.shared.b16 {%0,%1,%2,%3}, [%4];"
        : "=r"(r[0]), "=r"(r[1]), "=r"(r[2]), "=r"(r[3]) : "r"(addr));
}
__device__ __forceinline__ void mma16816(float* c, const uint32_t* a, const uint32_t* b) {
    asm volatile("mma.sync.aligned.m16n8k16.row.col.f32.f16.f16.f32 "
        "{%0,%1,%2,%3}, {%4,%5,%6,%7}, {%8,%9}, {%0,%1,%2,%3};"
        : "+f"(c[0]), "+f"(c[1]), "+f"(c[2]), "+f"(c[3])
        : "r"(a[0]), "r"(a[1]), "r"(a[2]), "r"(a[3]), "r"(b[0]), "r"(b[1]));
}
__device__ __forceinline__ void cpa16(uint32_t dst, const void* src) {
    asm volatile("cp.async.cg.shared.global [%0], [%1], 16;" :: "r"(dst), "l"(src) : "memory");
}
__device__ __forceinline__ void hsplit(float v, uint16_t &h, uint16_t &l) {
    __half hh = __float2half_rn(v);
    h = __half_as_ushort(hh);
    l = __half_as_ushort(__float2half_rn(v - __half2float(hh)));
}
__device__ __forceinline__ uint32_t pack2h(float a, float b) {
    __half2 h = __floats2half2_rn(a, b);
    return *(uint32_t*)&h;
}

// ---------------- aux kernels ----------------
__global__ void zero_stats_k(int nTotal) {
    const int i = threadIdx.x;   // 512
    if (i < 256) ((float*)g_sums)[i] = 0.f;
    else ((float*)g_sumsq)[i - 256] = 0.f;
#pragma unroll
    for (int j = 0; j < 4; ++j) {
        ((uint32_t*)g_biasHi)[i + j * 512] = 0u;
        ((uint32_t*)g_biasLo)[i + j * 512] = 0u;
    }
    if (i < 32) ((uint32_t*)(g_fS + (size_t)nTotal * 64))[i] = 0u;
    else if (i < 64) ((uint32_t*)(g_aS + (size_t)nTotal * 64))[i - 32] = 0u;
}

// Build one packed b16x2 frag reg from the scaled weight plane.
__device__ __forceinline__ uint32_t frag_reg(const float* __restrict__ src,
                                             const float* __restrict__ sck,
                                             int kk, int nn, int plane) {
    const float s0 = sck ? sck[kk] : 1.f;
    const float s1 = sck ? sck[kk + 1] : 1.f;
    uint16_t h0, l0, h1, l1;
    hsplit(src[kk * 64 + nn] * s0 * WSCALE, h0, l0);
    hsplit(src[(kk + 1) * 64 + nn] * s1 * WSCALE, h1, l1);
    const uint16_t a = plane ? l0 : h0;
    const uint16_t b = plane ? l1 : h1;
    return (uint32_t)a | ((uint32_t)b << 16);
}

__device__ __forceinline__ void write_frags(const float* __restrict__ src,
                                            const float* __restrict__ sck,
                                            __half* __restrict__ dstTap, int tid) {
#pragma unroll
    for (int i = 0; i < 4; ++i) {
        const int idx = tid + i * 256;           // 0..1023 uint4 slots
        const int lane = idx & 31;
        const int chunk = idx >> 5;              // 0..31: q*8 + wn*4 + c
        const int q = chunk >> 3, wn = (chunk >> 2) & 1, c = chunk & 3;
        const int plane = c >> 1, p = c & 1;
        const int m = lane & 3, nr = lane >> 2;
        const int k0 = 16 * q;
        const int n0 = wn * 32 + 16 * p + nr;
        uint4 o;
        o.x = frag_reg(src, sck, k0 + 2 * m,     n0,     plane);
        o.y = frag_reg(src, sck, k0 + 2 * m,     n0 + 8, plane);
        o.z = frag_reg(src, sck, k0 + 8 + 2 * m, n0,     plane);
        o.w = frag_reg(src, sck, k0 + 8 + 2 * m, n0 + 8, plane);
        ((uint4*)dstTap)[idx] = o;
    }
}

// plain weights [9][c][o] -> fragment layout (tensors 0 and 2)
__global__ void prep_plain_k(const float* __restrict__ w1, const float* __restrict__ w2) {
    const int t = (blockIdx.x < KTAPS) ? 0 : 2;
    const int k = blockIdx.x % KTAPS;
    const float* src = ((t == 0) ? w1 : w2) + k * 4096;
    __half* dst = g_wFrag + (size_t)t * FRAG_TENSOR_HALVES + (size_t)k * FRAG_TAP_HALVES;
    write_frags(src, nullptr, dst, threadIdx.x);
}

// fold BN(stage) into weights -> fragment layout; bias_k[o] = 256*sum_c shift[c]*W[c,o]
__global__ void prep_fold_k(const float* __restrict__ w, int tensor, int stage,
                            const float* __restrict__ gamma,
                            const float* __restrict__ beta, float invN) {
    __shared__ float sc[64], sh[64];
    const int k = blockIdx.x, tid = threadIdx.x;
    if (tid < 64) {
        const float m = g_sums[stage][tid] * invN;
        const float v = g_sumsq[stage][tid] * invN - m * m;
        const float a = gamma[tid] * rsqrtf(v + EPS_BN);
        sc[tid] = a;
        sh[tid] = beta[tid] - m * a;
    }
    __syncthreads();
    const float* src = w + (size_t)k * 4096;
    __half* dst = g_wFrag + (size_t)tensor * FRAG_TENSOR_HALVES + (size_t)k * FRAG_TAP_HALVES;
    write_frags(src, sc, dst, tid);
    if (tid < 64) {
        float s = 0.f;
#pragma unroll 8
        for (int c = 0; c < 64; ++c) s += sh[c] * src[c * 64 + tid];
        uint16_t h, l;
        hsplit(s * WSCALE, h, l);
        g_biasHi[tensor * 1024 + tid * 16 + k] = __ushort_as_half(h);
        g_biasLo[tensor * 1024 + tid * 16 + k] = __ushort_as_half(l);
    }
}

// fp32 features -> fp16 rows (once)
__global__ __launch_bounds__(256)
void split_k(const float* __restrict__ src, __half* __restrict__ dst, int nTotal) {
    const int row = blockIdx.x * 256 + threadIdx.x;
    if (row >= nTotal) return;
    const float4* s = (const float4*)(src + (size_t)row * CCH);
    uint4* d = (uint4*)(dst + (size_t)row * 64);
#pragma unroll
    for (int g = 0; g < 8; ++g) {
        const float4 v0 = s[2 * g], v1 = s[2 * g + 1];
        uint4 o;
        o.x = pack2h(v0.x, v0.y);
        o.y = pack2h(v0.z, v0.w);
        o.z = pack2h(v1.x, v1.y);
        o.w = pack2h(v1.z, v1.w);
        d[g] = o;
    }
}

// ---------------- main conv kernel (fp16 2-term, cp.async 3-stage A pipeline) ----------------
template <bool HAS_BIAS, bool OUT_PLANES>
__global__ __launch_bounds__(NTHR, 3)
void conv_mma_k(const __half* __restrict__ src,   // [N+1][64] fp16
                const int* __restrict__ nbr, int wtIdx,
                float* __restrict__ dstF, __half* __restrict__ dstP,
                int nTotal, int stage)
{
    extern __shared__ __align__(128) char smemc[];
    __shared__ uint4 sBBh[128];       // bias hi [64 o][16 taps] fp16
    __shared__ uint4 sBBl[128];
    __shared__ int   sNbr[128 * KTAPS];  // neighbor ids, all rows x taps

    const int tid   = threadIdx.x;
    const int lane  = tid & 31;
    const int wid   = tid >> 5;
    const int nBase = blockIdx.x * TN;
    const bool rowOK = (nBase + tid) < nTotal;

    const uint32_t sbase = smem_u32(smemc);
    // 2M x 2N warp grid: warp tile = 64 rows x 32 outch
    const int wm = wid & 1, wn = wid >> 1;
    const int rowBase = wm * 64;
    const int colBase = wn * 32;
    const int lsw = lane & 7, l15 = lane & 15, l16 = lane >> 4;

    // neighbor table (coalesced fill; invalid rows -> pad index nTotal)
#pragma unroll
    for (int j = 0; j < KTAPS; ++j)
        sNbr[tid * KTAPS + j] = rowOK ? nbr[(size_t)(nBase + tid) * KTAPS + j] : nTotal;

    if (HAS_BIAS) {
        sBBh[tid] = ((const uint4*)(g_biasHi + wtIdx * 1024))[tid];
        sBBl[tid] = ((const uint4*)(g_biasLo + wtIdx * 1024))[tid];
    }

    float C[4][4][4];
#pragma unroll
    for (int mt = 0; mt < 4; ++mt)
#pragma unroll
        for (int nt = 0; nt < 4; ++nt)
#pragma unroll
            for (int i = 0; i < 4; ++i) C[mt][nt][i] = 0.f;

    // B fragments: [tap][q][wn][chunk][lane] uint4
    const uint4* bF = (const uint4*)(g_wFrag + (size_t)wtIdx * FRAG_TENSOR_HALVES) + lane;

    // cooperative gather: 8 lanes per row, 4 rows per cp.async wave (full 128B lines)
    const int gRow0  = (wid << 5) + (lane >> 3);   // +4 per it
    const int gChunk = lane & 7;

    auto cpaTap = [&](int k) {
        const uint32_t ab = sbase + (uint32_t)(k % NSTAGE) * STAGE_BYTES;
#pragma unroll
        for (int it = 0; it < 8; ++it) {
            const int rl = gRow0 + (it << 2);
            const int nidx = sNbr[rl * KTAPS + k];
            cpa16(ab + (uint32_t)(rl * 128 + ((gChunk ^ (rl & 7)) << 4)),
                  src + (size_t)nidx * 64 + (gChunk << 3));
        }
        asm volatile("cp.async.commit_group;" ::: "memory");
    };

    __syncthreads();                 // sNbr visible to all warps
    cpaTap(0);
    cpaTap(1);

    for (int k = 0; k < KTAPS; ++k) {
        // tap k data complete for THIS thread (<=1 newer group pending)
        if (k < KTAPS - 1)
            asm volatile("cp.async.wait_group 1;" ::: "memory");
        else
            asm volatile("cp.async.wait_group 0;" ::: "memory");
        __syncthreads();             // all threads' tap-k copies landed; stage (k-1)%3 free

        if (k + 2 < KTAPS) cpaTap(k + 2);   // fills stage (k+2)%3 == (k-1)%3

        const uint32_t ab = sbase + (uint32_t)(k % NSTAGE) * STAGE_BYTES;
#pragma unroll
        for (int q = 0; q < 4; ++q) {
            const int kg = 2 * q + l16;
            uint32_t a_[4][4];
#pragma unroll
            for (int mt = 0; mt < 4; ++mt) {
                const uint32_t off =
                    (uint32_t)((rowBase + mt * 16 + l15) * 128 + ((kg ^ lsw) << 4));
                ldsm4(a_[mt], ab + off);
            }
            // B fragments direct from gmem (L1-hot, fully coalesced)
            const uint4* bq = bF + (size_t)(((k * 4 + q) * 2 + wn) * 4) * 32;
            const uint4 f0 = bq[0], f1 = bq[32], f2 = bq[64], f3 = bq[96];
            uint32_t bh[4][2], bl[4][2];
            bh[0][0] = f0.x; bh[1][0] = f0.y; bh[0][1] = f0.z; bh[1][1] = f0.w;
            bh[2][0] = f1.x; bh[3][0] = f1.y; bh[2][1] = f1.z; bh[3][1] = f1.w;
            bl[0][0] = f2.x; bl[1][0] = f2.y; bl[0][1] = f2.z; bl[1][1] = f2.w;
            bl[2][0] = f3.x; bl[3][0] = f3.y; bl[2][1] = f3.z; bl[3][1] = f3.w;
#pragma unroll
            for (int mt = 0; mt < 4; ++mt)
#pragma unroll
                for (int nt = 0; nt < 4; ++nt) {
                    mma16816(C[mt][nt], a_[mt], bh[nt]);
                    mma16816(C[mt][nt], a_[mt], bl[nt]);
                }
        }
    }

    // ---- bias MMA: C += V(128x16) * B(16x64); V fragments built from sNbr ----
    if (HAS_BIAS) {
        uint32_t av[4][4];
        const int fr = lane >> 2, fc = (lane & 3) * 2;
#pragma unroll
        for (int mt = 0; mt < 4; ++mt) {
            const int r0 = rowBase + mt * 16 + fr;
            const int r1 = r0 + 8;
#pragma unroll
            for (int j = 0; j < 4; ++j) {
                const int rr = (j & 1) ? r1 : r0;
                const int c0 = fc + ((j >> 1) << 3);
                uint32_t lo = 0u, hi = 0u;
                if (c0     < KTAPS && sNbr[rr * KTAPS + c0]     < nTotal) lo = 0x3C00u;
                if (c0 + 1 < KTAPS && sNbr[rr * KTAPS + c0 + 1] < nTotal) hi = 0x3C00u;
                av[mt][j] = lo | (hi << 16);
            }
        }
        const uint32_t bhb = smem_u32(sBBh);
        const uint32_t blb = smem_u32(sBBl);
        uint32_t bbh[4][2], bbl[4][2];
#pragma unroll
        for (int p = 0; p < 2; ++p) {
            const uint32_t off = (uint32_t)((colBase + 16 * p + l15) * 32 + l16 * 16);
            uint32_t r[4];
            ldsm4(r, bhb + off);
            bbh[2*p][0] = r[0]; bbh[2*p+1][0] = r[1];
            bbh[2*p][1] = r[2]; bbh[2*p+1][1] = r[3];
            ldsm4(r, blb + off);
            bbl[2*p][0] = r[0]; bbl[2*p+1][0] = r[1];
            bbl[2*p][1] = r[2]; bbl[2*p+1][1] = r[3];
        }
#pragma unroll
        for (int mt = 0; mt < 4; ++mt)
#pragma unroll
            for (int nt = 0; nt < 4; ++nt) {
                mma16816(C[mt][nt], av[mt], bbh[nt]);
                mma16816(C[mt][nt], av[mt], bbl[nt]);
            }
    }

    // ---- epilogue: descale + leaky -> smem fp32 tile -> store + stats ----
    __syncthreads();
    float* sC = (float*)smemc;                   // [128][SC_STRIDE] = 34816B <= 48K
    const int fg = lane >> 2, ft2 = (lane & 3) * 2;
#pragma unroll
    for (int mt = 0; mt < 4; ++mt)
#pragma unroll
        for (int nt = 0; nt < 4; ++nt) {
            float* c = C[mt][nt];
#pragma unroll
            for (int i = 0; i < 4; ++i) {
                const float v = c[i] * INV_WSCALE;
                c[i] = (v > 0.f) ? v : LEAK * v;
            }
            const int r0 = rowBase + mt * 16 + fg;
            const int col = colBase + nt * 8 + ft2;
            *(float2*)&sC[r0 * SC_STRIDE + col]       = make_float2(c[0], c[1]);
            *(float2*)&sC[(r0 + 8) * SC_STRIDE + col] = make_float2(c[2], c[3]);
        }
    __syncthreads();

    if (rowOK) {
        const float4* rowp = (const float4*)(sC + tid * SC_STRIDE);
        if (OUT_PLANES) {
            uint4* d = (uint4*)(dstP + (size_t)(nBase + tid) * 64);
#pragma unroll
            for (int g = 0; g < 8; ++g) {
                const float4 v0 = rowp[2 * g], v1 = rowp[2 * g + 1];
                uint4 o;
                o.x = pack2h(v0.x, v0.y);
                o.y = pack2h(v0.z, v0.w);
                o.z = pack2h(v1.x, v1.y);
                o.w = pack2h(v1.z, v1.w);
                d[g] = o;
            }
        } else {
            float4* drow = (float4*)(dstF + (size_t)(nBase + tid) * CCH);
#pragma unroll
            for (int c4 = 0; c4 < 16; ++c4) drow[c4] = rowp[c4];
        }
    }

    {
        const int ch = tid >> 1, half = tid & 1;
        float s = 0.f, s2 = 0.f;
#pragma unroll 8
        for (int i = 0; i < 64; ++i) {
            const float v = sC[(half * 64 + i) * SC_STRIDE + ch];
            s += v; s2 += v * v;
        }
        s  += __shfl_xor_sync(0xffffffffu, s, 1);
        s2 += __shfl_xor_sync(0xffffffffu, s2, 1);
        if (!half) {
            atomicAdd(&g_sums[stage][ch], s);
            atomicAdd(&g_sumsq[stage][ch], s2);
        }
    }
}

// out = BN3(out) + BN1(y2); coefficients for stages 1,3 computed inline
__global__ __launch_bounds__(256)
void final_k(float* __restrict__ out, const float* __restrict__ y2,
             const float* __restrict__ g1_, const float* __restrict__ b1_,
             const float* __restrict__ g3_, const float* __restrict__ b3_,
             float invN, int total4)
{
    __shared__ float c1[64], s1[64], c3[64], s3[64];
    const int tid = threadIdx.x;
    if (tid < 64) {
        const float m1 = g_sums[1][tid] * invN;
        const float v1 = g_sumsq[1][tid] * invN - m1 * m1;
        const float a1 = g1_[tid] * rsqrtf(v1 + EPS_BN);
        c1[tid] = a1; s1[tid] = b1_[tid] - m1 * a1;
        const float m3 = g_sums[3][tid] * invN;
        const float v3 = g_sumsq[3][tid] * invN - m3 * m3;
        const float a3 = g3_[tid] * rsqrtf(v3 + EPS_BN);
        c3[tid] = a3; s3[tid] = b3_[tid] - m3 * a3;
    }
    __syncthreads();
    const int i = blockIdx.x * 256 + tid;
    if (i >= total4) return;
    float4 a = ((float4*)out)[i];
    const float4 b = ((const float4*)y2)[i];
    const int c = (i * 4) & 63;
    a.x = fmaf(a.x, c3[c + 0], s3[c + 0]) + fmaf(b.x, c1[c + 0], s1[c + 0]);
    a.y = fmaf(a.y, c3[c + 1], s3[c + 1]) + fmaf(b.y, c1[c + 1], s1[c + 1]);
    a.z = fmaf(a.z, c3[c + 2], s3[c + 2]) + fmaf(b.z, c1[c + 2], s1[c + 2]);
    a.w = fmaf(a.w, c3[c + 3], s3[c + 3]) + fmaf(b.w, c1[c + 3], s1[c + 3]);
    ((float4*)out)[i] = a;
}

// ---------------- launcher ----------------
extern "C" void kernel_launch(void* const* d_in, const int* in_sizes, int n_in,
                              void* d_out, int out_size)
{
    const float* features = (const float*)d_in[0];
    const float* w1   = (const float*)d_in[1];
    const float* w1_2 = (const float*)d_in[2];
    const float* w2   = (const float*)d_in[3];
    const float* w3   = (const float*)d_in[4];
    const float* g0   = (const float*)d_in[5];
    const float* b0   = (const float*)d_in[6];
    const float* g0_2 = (const float*)d_in[7];
    const float* b0_2 = (const float*)d_in[8];
    const float* g1   = (const float*)d_in[9];
    const float* b1   = (const float*)d_in[10];
    const float* g2   = (const float*)d_in[11];
    const float* b2   = (const float*)d_in[12];
    const int*   nbr13 = (const int*)d_in[13];
    const int*   nbr31 = (const int*)d_in[14];

    const int nTotal = in_sizes[0] / CCH;
    const float invN = 1.0f / (float)nTotal;
    const int grid   = (nTotal + TN - 1) / TN;
    const int gridS  = (nTotal + 255) / 256;

    cudaFuncSetAttribute(conv_mma_k<false, true>,
                         cudaFuncAttributeMaxDynamicSharedMemorySize, DSM_BYTES);
    cudaFuncSetAttribute(conv_mma_k<true, false>,
                         cudaFuncAttributeMaxDynamicSharedMemorySize, DSM_BYTES);

    float* bufB = nullptr;
    __half *fS = nullptr, *aS = nullptr;
    cudaGetSymbolAddress((void**)&bufB, g_bufB);
    cudaGetSymbolAddress((void**)&fS, g_fS);
    cudaGetSymbolAddress((void**)&aS, g_aS);
    float* out = (float*)d_out;

    zero_stats_k<<<1, 512>>>(nTotal);
    prep_plain_k<<<2 * KTAPS, 256>>>(w1, w2);
    split_k<<<gridS, 256>>>(features, fS, nTotal);

    // shortcut: conv(nbr13,w1)[planes,stats0] -> fold BN0 into w1_2 -> conv(nbr31)[fp32,stats1]
    conv_mma_k<false, true ><<<grid, NTHR, DSM_BYTES>>>(fS, nbr13, 0, nullptr, aS, nTotal, 0);
    prep_fold_k<<<KTAPS, 256>>>(w1_2, 1, 0, g0, b0, invN);
    conv_mma_k<true , false><<<grid, NTHR, DSM_BYTES>>>(aS, nbr31, 1, bufB, nullptr, nTotal, 1);

    // main: conv(nbr31,w2)[planes,stats2] -> fold BN2 into w3 -> conv(nbr13,w3)[fp32,stats3]
    conv_mma_k<false, true ><<<grid, NTHR, DSM_BYTES>>>(fS, nbr31, 2, nullptr, aS, nTotal, 2);
    prep_fold_k<<<KTAPS, 256>>>(w3, 3, 2, g1, b1, invN);
    conv_mma_k<true , false><<<grid, NTHR, DSM_BYTES>>>(aS, nbr13, 3, out, nullptr, nTotal, 3);

    // out = BN3(out) + BN1(bufB)
    const int total4 = nTotal * CCH / 4;
    final_k<<<(total4 + 255) / 256, 256>>>(out, bufB, g0_2, b0_2, g2, b2, invN, total4);
}

// round 13
// speedup vs baseline: 3.3243x; 3.3243x over previous
#include <cuda_runtime.h>
#include <cuda_fp16.h>
#include <cstdint>

// ---------------- problem constants ----------------
#define NMAX   200000
#define CCH    64
#define KTAPS  9
#define TN     128          // rows per block (MMA M)
#define NTHR   128
#define LEAK   0.01f
#define EPS_BN 1e-5f
#define WSCALE 256.0f       // weight scaling (keeps fp16 lo-plane normal)
#define INV_WSCALE (1.0f / 256.0f)

// dynamic smem: A stage 16K x2 (compute) / fp32 epilogue tile 34816B
#define STAGE_BYTES 16384
#define DSM_BYTES 34816
#define SC_STRIDE 68        // epilogue fp32 tile stride (floats)

// B fragment layout: halves per tap = 4q * (2wn*4c) chunks * 32 lanes * 8 = 8192
#define FRAG_TAP_HALVES   8192
#define FRAG_TENSOR_HALVES (KTAPS * FRAG_TAP_HALVES)   // 73728

// ---------------- scratch (no cudaMalloc allowed) ----------------
__device__ float g_bufB[(size_t)NMAX * CCH];
// fp16 feature rows: [row][64 fp16]; row nTotal = zero pad
__device__ __half g_fS [((size_t)NMAX + 1) * 64];
__device__ __half g_aSa[((size_t)NMAX + 1) * 64];   // shortcut branch planes
__device__ __half g_aSb[((size_t)NMAX + 1) * 64];   // main branch planes
__device__ __half g_wFrag[4 * FRAG_TENSOR_HALVES];  // B in per-lane MMA fragment layout
__device__ __half g_biasHi[4 * 64 * 16];            // [tensor][o*16 + tap], x256
__device__ __half g_biasLo[4 * 64 * 16];
__device__ float g_sums [4][CCH];
__device__ float g_sumsq[4][CCH];

// ---------------- helpers ----------------
__device__ __forceinline__ uint32_t smem_u32(const void* p) {
    uint32_t a;
    asm("{ .reg .u64 t; cvta.to.shared.u64 t, %1; cvt.u32.u64 %0, t; }" : "=r"(a) : "l"(p));
    return a;
}
__device__ __forceinline__ void ldsm4(uint32_t* r, uint32_t addr) {
    asm volatile("ldmatrix.sync.aligned.m8n8.x4.shared.b16 {%0,%1,%2,%3}, [%4];"
        : "=r"(r[0]), "=r"(r[1]), "=r"(r[2]), "=r"(r[3]) : "r"(addr));
}
__device__ __forceinline__ void mma16816(float* c, const uint32_t* a, const uint32_t* b) {
    asm volatile("mma.sync.aligned.m16n8k16.row.col.f32.f16.f16.f32 "
        "{%0,%1,%2,%3}, {%4,%5,%6,%7}, {%8,%9}, {%0,%1,%2,%3};"
        : "+f"(c[0]), "+f"(c[1]), "+f"(c[2]), "+f"(c[3])
        : "r"(a[0]), "r"(a[1]), "r"(a[2]), "r"(a[3]), "r"(b[0]), "r"(b[1]));
}
__device__ __forceinline__ void hsplit(float v, uint16_t &h, uint16_t &l) {
    __half hh = __float2half_rn(v);
    h = __half_as_ushort(hh);
    l = __half_as_ushort(__float2half_rn(v - __half2float(hh)));
}
__device__ __forceinline__ uint32_t pack2h(float a, float b) {
    __half2 h = __floats2half2_rn(a, b);
    return *(uint32_t*)&h;
}

// ---------------- aux kernels ----------------
__global__ void zero_stats_k(int nTotal) {
    const int i = threadIdx.x;   // 512
    if (i < 256) ((float*)g_sums)[i] = 0.f;
    else ((float*)g_sumsq)[i - 256] = 0.f;
#pragma unroll
    for (int j = 0; j < 4; ++j) {
        ((uint32_t*)g_biasHi)[i + j * 512] = 0u;
        ((uint32_t*)g_biasLo)[i + j * 512] = 0u;
    }
    if (i < 32) ((uint32_t*)(g_fS + (size_t)nTotal * 64))[i] = 0u;
    else if (i < 64) ((uint32_t*)(g_aSa + (size_t)nTotal * 64))[i - 32] = 0u;
    else if (i < 96) ((uint32_t*)(g_aSb + (size_t)nTotal * 64))[i - 64] = 0u;
}

// Build one packed b16x2 frag reg from the scaled weight plane.
__device__ __forceinline__ uint32_t frag_reg(const float* __restrict__ src,
                                             const float* __restrict__ sck,
                                             int kk, int nn, int plane) {
    const float s0 = sck ? sck[kk] : 1.f;
    const float s1 = sck ? sck[kk + 1] : 1.f;
    uint16_t h0, l0, h1, l1;
    hsplit(src[kk * 64 + nn] * s0 * WSCALE, h0, l0);
    hsplit(src[(kk + 1) * 64 + nn] * s1 * WSCALE, h1, l1);
    const uint16_t a = plane ? l0 : h0;
    const uint16_t b = plane ? l1 : h1;
    return (uint32_t)a | ((uint32_t)b << 16);
}

__device__ __forceinline__ void write_frags(const float* __restrict__ src,
                                            const float* __restrict__ sck,
                                            __half* __restrict__ dstTap, int tid) {
#pragma unroll
    for (int i = 0; i < 4; ++i) {
        const int idx = tid + i * 256;           // 0..1023 uint4 slots
        const int lane = idx & 31;
        const int chunk = idx >> 5;              // 0..31: q*8 + wn*4 + c
        const int q = chunk >> 3, wn = (chunk >> 2) & 1, c = chunk & 3;
        const int plane = c >> 1, p = c & 1;
        const int m = lane & 3, nr = lane >> 2;
        const int k0 = 16 * q;
        const int n0 = wn * 32 + 16 * p + nr;
        uint4 o;
        o.x = frag_reg(src, sck, k0 + 2 * m,     n0,     plane);
        o.y = frag_reg(src, sck, k0 + 2 * m,     n0 + 8, plane);
        o.z = frag_reg(src, sck, k0 + 8 + 2 * m, n0,     plane);
        o.w = frag_reg(src, sck, k0 + 8 + 2 * m, n0 + 8, plane);
        ((uint4*)dstTap)[idx] = o;
    }
}

// plain weights [9][c][o] -> fragment layout (tensors 0 and 2)
__global__ void prep_plain_k(const float* __restrict__ w1, const float* __restrict__ w2) {
    const int t = (blockIdx.x < KTAPS) ? 0 : 2;
    const int k = blockIdx.x % KTAPS;
    const float* src = ((t == 0) ? w1 : w2) + k * 4096;
    __half* dst = g_wFrag + (size_t)t * FRAG_TENSOR_HALVES + (size_t)k * FRAG_TAP_HALVES;
    write_frags(src, nullptr, dst, threadIdx.x);
}

// fold BN(stage) into weights -> fragment layout; bias_k[o] = 256*sum_c shift[c]*W[c,o]
// merged: blocks 0..8 -> (wA, tensor1, stageA), blocks 9..17 -> (wB, tensor3, stageB)
__global__ void prep_fold2_k(const float* __restrict__ wA, const float* __restrict__ wB,
                             const float* __restrict__ gA, const float* __restrict__ bA,
                             const float* __restrict__ gB, const float* __restrict__ bB,
                             float invN) {
    __shared__ float sc[64], sh[64];
    const int sel = blockIdx.x / KTAPS;           // 0 or 1
    const int k = blockIdx.x % KTAPS, tid = threadIdx.x;
    const float* w = sel ? wB : wA;
    const float* gamma = sel ? gB : gA;
    const float* beta  = sel ? bB : bA;
    const int stage = sel ? 2 : 0;
    const int tensor = sel ? 3 : 1;
    if (tid < 64) {
        const float m = g_sums[stage][tid] * invN;
        const float v = g_sumsq[stage][tid] * invN - m * m;
        const float a = gamma[tid] * rsqrtf(v + EPS_BN);
        sc[tid] = a;
        sh[tid] = beta[tid] - m * a;
    }
    __syncthreads();
    const float* src = w + (size_t)k * 4096;
    __half* dst = g_wFrag + (size_t)tensor * FRAG_TENSOR_HALVES + (size_t)k * FRAG_TAP_HALVES;
    write_frags(src, sc, dst, tid);
    if (tid < 64) {
        float s = 0.f;
#pragma unroll 8
        for (int c = 0; c < 64; ++c) s += sh[c] * src[c * 64 + tid];
        uint16_t h, l;
        hsplit(s * WSCALE, h, l);
        g_biasHi[tensor * 1024 + tid * 16 + k] = __ushort_as_half(h);
        g_biasLo[tensor * 1024 + tid * 16 + k] = __ushort_as_half(l);
    }
}

// fp32 features -> fp16 rows (once)
__global__ __launch_bounds__(256)
void split_k(const float* __restrict__ src, __half* __restrict__ dst, int nTotal) {
    const int row = blockIdx.x * 256 + threadIdx.x;
    if (row >= nTotal) return;
    const float4* s = (const float4*)(src + (size_t)row * CCH);
    uint4* d = (uint4*)(dst + (size_t)row * 64);
#pragma unroll
    for (int g = 0; g < 8; ++g) {
        const float4 v0 = s[2 * g], v1 = s[2 * g + 1];
        uint4 o;
        o.x = pack2h(v0.x, v0.y);
        o.y = pack2h(v0.z, v0.w);
        o.z = pack2h(v1.x, v1.y);
        o.w = pack2h(v1.z, v1.w);
        d[g] = o;
    }
}

// ---------------- main conv kernel (fp16 2-term; two independent convs via gridDim.y) ----------------
template <bool HAS_BIAS, bool OUT_PLANES>
__global__ __launch_bounds__(NTHR, 3)
void conv_mma_k(const __half* __restrict__ src0, const __half* __restrict__ src1,
                const int* __restrict__ nbr0, const int* __restrict__ nbr1,
                int wt0, int wt1,
                float* __restrict__ dstF0, float* __restrict__ dstF1,
                __half* __restrict__ dstP0, __half* __restrict__ dstP1,
                int nTotal, int stage0, int stage1)
{
    extern __shared__ __align__(128) char smemc[];
    __shared__ uint4 sBBh[128];       // bias hi [64 o][16 taps] fp16
    __shared__ uint4 sBBl[128];
    __shared__ int   sNbr[128 * KTAPS];  // neighbor ids, all rows x taps

    const int sel = blockIdx.y;
    const __half* __restrict__ src = sel ? src1 : src0;
    const int*    __restrict__ nbr = sel ? nbr1 : nbr0;
    const int wtIdx = sel ? wt1 : wt0;
    float* __restrict__ dstF = sel ? dstF1 : dstF0;
    __half* __restrict__ dstP = sel ? dstP1 : dstP0;
    const int stage = sel ? stage1 : stage0;

    const int tid   = threadIdx.x;
    const int lane  = tid & 31;
    const int wid   = tid >> 5;
    const int nBase = blockIdx.x * TN;
    const bool rowOK = (nBase + tid) < nTotal;

    const uint32_t sbase = smem_u32(smemc);
    // 2M x 2N warp grid: warp tile = 64 rows x 32 outch
    const int wm = wid & 1, wn = wid >> 1;
    const int rowBase = wm * 64;
    const int colBase = wn * 32;
    const int lsw = lane & 7, l15 = lane & 15, l16 = lane >> 4;

    // neighbor table (coalesced fill; invalid rows -> pad index nTotal)
#pragma unroll
    for (int j = 0; j < KTAPS; ++j)
        sNbr[tid * KTAPS + j] = rowOK ? nbr[(size_t)(nBase + tid) * KTAPS + j] : nTotal;

    if (HAS_BIAS) {
        sBBh[tid] = ((const uint4*)(g_biasHi + wtIdx * 1024))[tid];
        sBBl[tid] = ((const uint4*)(g_biasLo + wtIdx * 1024))[tid];
    }

    float C[4][4][4];
#pragma unroll
    for (int mt = 0; mt < 4; ++mt)
#pragma unroll
        for (int nt = 0; nt < 4; ++nt)
#pragma unroll
            for (int i = 0; i < 4; ++i) C[mt][nt][i] = 0.f;

    // B fragments: [tap][q][wn][chunk][lane] uint4
    const uint4* bF = (const uint4*)(g_wFrag + (size_t)wtIdx * FRAG_TENSOR_HALVES) + lane;

    // cooperative gather: 8 lanes per row, 4 rows per instruction (full 128B lines)
    const int gRow0  = (wid << 5) + (lane >> 3);   // +4 per it
    const int gChunk = lane & 7;
    uint4 pa[8];

    auto ldgA = [&](int k) {
#pragma unroll
        for (int it = 0; it < 8; ++it) {
            const int rl = gRow0 + (it << 2);
            const int nidx = sNbr[rl * KTAPS + k];
            pa[it] = *(const uint4*)(src + (size_t)nidx * 64 + (gChunk << 3));
        }
    };
    auto stsA = [&](int s) {
        char* ab = smemc + s * STAGE_BYTES;
#pragma unroll
        for (int it = 0; it < 8; ++it) {
            const int rl = gRow0 + (it << 2);
            *(uint4*)(ab + rl * 128 + ((gChunk ^ (rl & 7)) << 4)) = pa[it];
        }
    };

    __syncthreads();                 // sNbr visible to all warps
    ldgA(0);
    stsA(0);

    for (int k = 0; k < KTAPS; ++k) {
        __syncthreads();             // stage k&1 visible; stage (k+1)&1 free

        if (k < KTAPS - 1) ldgA(k + 1);  // full-line LDGs hide under MMAs below

        const uint32_t ab = sbase + (k & 1) * STAGE_BYTES;
#pragma unroll
        for (int q = 0; q < 4; ++q) {
            const int kg = 2 * q + l16;
            uint32_t a_[4][4];
#pragma unroll
            for (int mt = 0; mt < 4; ++mt) {
                const uint32_t off =
                    (uint32_t)((rowBase + mt * 16 + l15) * 128 + ((kg ^ lsw) << 4));
                ldsm4(a_[mt], ab + off);
            }
            // B fragments direct from gmem (L1-hot, fully coalesced)
            const uint4* bq = bF + (size_t)(((k * 4 + q) * 2 + wn) * 4) * 32;
            const uint4 f0 = bq[0], f1 = bq[32], f2 = bq[64], f3 = bq[96];
            uint32_t bh[4][2], bl[4][2];
            bh[0][0] = f0.x; bh[1][0] = f0.y; bh[0][1] = f0.z; bh[1][1] = f0.w;
            bh[2][0] = f1.x; bh[3][0] = f1.y; bh[2][1] = f1.z; bh[3][1] = f1.w;
            bl[0][0] = f2.x; bl[1][0] = f2.y; bl[0][1] = f2.z; bl[1][1] = f2.w;
            bl[2][0] = f3.x; bl[3][0] = f3.y; bl[2][1] = f3.z; bl[3][1] = f3.w;
#pragma unroll
            for (int mt = 0; mt < 4; ++mt)
#pragma unroll
                for (int nt = 0; nt < 4; ++nt) {
                    mma16816(C[mt][nt], a_[mt], bh[nt]);
                    mma16816(C[mt][nt], a_[mt], bl[nt]);
                }
        }

        if (k < KTAPS - 1) stsA((k + 1) & 1);
    }

    // ---- bias MMA: C += V(128x16) * B(16x64); V fragments built from sNbr ----
    if (HAS_BIAS) {
        uint32_t av[4][4];
        const int fr = lane >> 2, fc = (lane & 3) * 2;
#pragma unroll
        for (int mt = 0; mt < 4; ++mt) {
            const int r0 = rowBase + mt * 16 + fr;
            const int r1 = r0 + 8;
#pragma unroll
            for (int j = 0; j < 4; ++j) {
                const int rr = (j & 1) ? r1 : r0;
                const int c0 = fc + ((j >> 1) << 3);
                uint32_t lo = 0u, hi = 0u;
                if (c0     < KTAPS && sNbr[rr * KTAPS + c0]     < nTotal) lo = 0x3C00u;
                if (c0 + 1 < KTAPS && sNbr[rr * KTAPS + c0 + 1] < nTotal) hi = 0x3C00u;
                av[mt][j] = lo | (hi << 16);
            }
        }
        const uint32_t bhb = smem_u32(sBBh);
        const uint32_t blb = smem_u32(sBBl);
        uint32_t bbh[4][2], bbl[4][2];
#pragma unroll
        for (int p = 0; p < 2; ++p) {
            const uint32_t off = (uint32_t)((colBase + 16 * p + l15) * 32 + l16 * 16);
            uint32_t r[4];
            ldsm4(r, bhb + off);
            bbh[2*p][0] = r[0]; bbh[2*p+1][0] = r[1];
            bbh[2*p][1] = r[2]; bbh[2*p+1][1] = r[3];
            ldsm4(r, blb + off);
            bbl[2*p][0] = r[0]; bbl[2*p+1][0] = r[1];
            bbl[2*p][1] = r[2]; bbl[2*p+1][1] = r[3];
        }
#pragma unroll
        for (int mt = 0; mt < 4; ++mt)
#pragma unroll
            for (int nt = 0; nt < 4; ++nt) {
                mma16816(C[mt][nt], av[mt], bbh[nt]);
                mma16816(C[mt][nt], av[mt], bbl[nt]);
            }
    }

    // ---- epilogue: descale + leaky -> smem fp32 tile -> store + stats ----
    __syncthreads();
    float* sC = (float*)smemc;                   // [128][SC_STRIDE] = 34816B
    const int fg = lane >> 2, ft2 = (lane & 3) * 2;
#pragma unroll
    for (int mt = 0; mt < 4; ++mt)
#pragma unroll
        for (int nt = 0; nt < 4; ++nt) {
            float* c = C[mt][nt];
#pragma unroll
            for (int i = 0; i < 4; ++i) {
                const float v = c[i] * INV_WSCALE;
                c[i] = (v > 0.f) ? v : LEAK * v;
            }
            const int r0 = rowBase + mt * 16 + fg;
            const int col = colBase + nt * 8 + ft2;
            *(float2*)&sC[r0 * SC_STRIDE + col]       = make_float2(c[0], c[1]);
            *(float2*)&sC[(r0 + 8) * SC_STRIDE + col] = make_float2(c[2], c[3]);
        }
    __syncthreads();

    if (rowOK) {
        const float4* rowp = (const float4*)(sC + tid * SC_STRIDE);
        if (OUT_PLANES) {
            uint4* d = (uint4*)(dstP + (size_t)(nBase + tid) * 64);
#pragma unroll
            for (int g = 0; g < 8; ++g) {
                const float4 v0 = rowp[2 * g], v1 = rowp[2 * g + 1];
                uint4 o;
                o.x = pack2h(v0.x, v0.y);
                o.y = pack2h(v0.z, v0.w);
                o.z = pack2h(v1.x, v1.y);
                o.w = pack2h(v1.z, v1.w);
                d[g] = o;
            }
        } else {
            float4* drow = (float4*)(dstF + (size_t)(nBase + tid) * CCH);
#pragma unroll
            for (int c4 = 0; c4 < 16; ++c4) drow[c4] = rowp[c4];
        }
    }

    {
        const int ch = tid >> 1, half = tid & 1;
        float s = 0.f, s2 = 0.f;
#pragma unroll 8
        for (int i = 0; i < 64; ++i) {
            const float v = sC[(half * 64 + i) * SC_STRIDE + ch];
            s += v; s2 += v * v;
        }
        s  += __shfl_xor_sync(0xffffffffu, s, 1);
        s2 += __shfl_xor_sync(0xffffffffu, s2, 1);
        if (!half) {
            atomicAdd(&g_sums[stage][ch], s);
            atomicAdd(&g_sumsq[stage][ch], s2);
        }
    }
}

// out = BN3(out) + BN1(y2); coefficients for stages 1,3 computed inline
__global__ __launch_bounds__(256)
void final_k(float* __restrict__ out, const float* __restrict__ y2,
             const float* __restrict__ g1_, const float* __restrict__ b1_,
             const float* __restrict__ g3_, const float* __restrict__ b3_,
             float invN, int total4)
{
    __shared__ float c1[64], s1[64], c3[64], s3[64];
    const int tid = threadIdx.x;
    if (tid < 64) {
        const float m1 = g_sums[1][tid] * invN;
        const float v1 = g_sumsq[1][tid] * invN - m1 * m1;
        const float a1 = g1_[tid] * rsqrtf(v1 + EPS_BN);
        c1[tid] = a1; s1[tid] = b1_[tid] - m1 * a1;
        const float m3 = g_sums[3][tid] * invN;
        const float v3 = g_sumsq[3][tid] * invN - m3 * m3;
        const float a3 = g3_[tid] * rsqrtf(v3 + EPS_BN);
        c3[tid] = a3; s3[tid] = b3_[tid] - m3 * a3;
    }
    __syncthreads();
    const int i = blockIdx.x * 256 + tid;
    if (i >= total4) return;
    float4 a = ((float4*)out)[i];
    const float4 b = ((const float4*)y2)[i];
    const int c = (i * 4) & 63;
    a.x = fmaf(a.x, c3[c + 0], s3[c + 0]) + fmaf(b.x, c1[c + 0], s1[c + 0]);
    a.y = fmaf(a.y, c3[c + 1], s3[c + 1]) + fmaf(b.y, c1[c + 1], s1[c + 1]);
    a.z = fmaf(a.z, c3[c + 2], s3[c + 2]) + fmaf(b.z, c1[c + 2], s1[c + 2]);
    a.w = fmaf(a.w, c3[c + 3], s3[c + 3]) + fmaf(b.w, c1[c + 3], s1[c + 3]);
    ((float4*)out)[i] = a;
}

// ---------------- launcher ----------------
extern "C" void kernel_launch(void* const* d_in, const int* in_sizes, int n_in,
                              void* d_out, int out_size)
{
    const float* features = (const float*)d_in[0];
    const float* w1   = (const float*)d_in[1];
    const float* w1_2 = (const float*)d_in[2];
    const float* w2   = (const float*)d_in[3];
    const float* w3   = (const float*)d_in[4];
    const float* g0   = (const float*)d_in[5];
    const float* b0   = (const float*)d_in[6];
    const float* g0_2 = (const float*)d_in[7];
    const float* b0_2 = (const float*)d_in[8];
    const float* g1   = (const float*)d_in[9];
    const float* b1   = (const float*)d_in[10];
    const float* g2   = (const float*)d_in[11];
    const float* b2   = (const float*)d_in[12];
    const int*   nbr13 = (const int*)d_in[13];
    const int*   nbr31 = (const int*)d_in[14];

    const int nTotal = in_sizes[0] / CCH;
    const float invN = 1.0f / (float)nTotal;
    const int grid   = (nTotal + TN - 1) / TN;
    const int gridS  = (nTotal + 255) / 256;

    cudaFuncSetAttribute(conv_mma_k<false, true>,
                         cudaFuncAttributeMaxDynamicSharedMemorySize, DSM_BYTES);
    cudaFuncSetAttribute(conv_mma_k<true, false>,
                         cudaFuncAttributeMaxDynamicSharedMemorySize, DSM_BYTES);

    float* bufB = nullptr;
    __half *fS = nullptr, *aSa = nullptr, *aSb = nullptr;
    cudaGetSymbolAddress((void**)&bufB, g_bufB);
    cudaGetSymbolAddress((void**)&fS,  g_fS);
    cudaGetSymbolAddress((void**)&aSa, g_aSa);
    cudaGetSymbolAddress((void**)&aSb, g_aSb);
    float* out = (float*)d_out;

    zero_stats_k<<<1, 512>>>(nTotal);
    prep_plain_k<<<2 * KTAPS, 256>>>(w1, w2);
    split_k<<<gridS, 256>>>(features, fS, nTotal);

    // phase A: conv0 (shortcut, nbr13, w1 -> aSa, stats0) || conv2 (main, nbr31, w2 -> aSb, stats2)
    {
        dim3 g2d(grid, 2);
        conv_mma_k<false, true><<<g2d, NTHR, DSM_BYTES>>>(
            fS, fS, nbr13, nbr31, 0, 2,
            nullptr, nullptr, aSa, aSb, nTotal, 0, 2);
    }

    // fold BN0 into w1_2 (tensor1) and BN2 into w3 (tensor3), one launch
    prep_fold2_k<<<2 * KTAPS, 256>>>(w1_2, w3, g0, b0, g1, b1, invN);

    // phase B: conv1 (aSa, nbr31, w1_2 -> bufB, stats1) || conv3 (aSb, nbr13, w3 -> out, stats3)
    {
        dim3 g2d(grid, 2);
        conv_mma_k<true, false><<<g2d, NTHR, DSM_BYTES>>>(
            aSa, aSb, nbr31, nbr13, 1, 3,
            bufB, out, nullptr, nullptr, nTotal, 1, 3);
    }

    // out = BN3(out) + BN1(bufB)
    const int total4 = nTotal * CCH / 4;
    final_k<<<(total4 + 255) / 256, 256>>>(out, bufB, g0_2, b0_2, g2, b2, invN, total4);
}

// round 14
// speedup vs baseline: 3.4431x; 1.0358x over previous
#include <cuda_runtime.h>
#include <cuda_fp16.h>
#include <cstdint>

// ---------------- problem constants ----------------
#define NMAX   200000
#define CCH    64
#define KTAPS  9
#define TN     128          // rows per block (MMA M)
#define NTHR   128
#define LEAK   0.01f
#define EPS_BN 1e-5f
#define WSCALE 256.0f       // weight scaling (keeps fp16 lo-plane normal)
#define INV_WSCALE (1.0f / 256.0f)

// dynamic smem: 2 stages x 32K (2 taps per stage) / fp32 epilogue tile 34816B
#define TAP_BYTES   16384
#define STAGE_BYTES 32768
#define DSM_BYTES   65536
#define SC_STRIDE 68        // epilogue fp32 tile stride (floats)

// B fragment layout: halves per tap = 4q * (2wn*4c) chunks * 32 lanes * 8 = 8192
#define FRAG_TAP_HALVES   8192
#define FRAG_TENSOR_HALVES (KTAPS * FRAG_TAP_HALVES)   // 73728

// ---------------- scratch (no cudaMalloc allowed) ----------------
__device__ float g_bufB[(size_t)NMAX * CCH];
// fp16 feature rows: [row][64 fp16]; row nTotal = zero pad
__device__ __half g_fS [((size_t)NMAX + 1) * 64];
__device__ __half g_aSa[((size_t)NMAX + 1) * 64];   // shortcut branch planes
__device__ __half g_aSb[((size_t)NMAX + 1) * 64];   // main branch planes
__device__ __half g_wFrag[4 * FRAG_TENSOR_HALVES];  // B in per-lane MMA fragment layout
__device__ __half g_biasHi[4 * 64 * 16];            // [tensor][o*16 + tap], x256
__device__ __half g_biasLo[4 * 64 * 16];
__device__ float g_sums [4][CCH];
__device__ float g_sumsq[4][CCH];

// ---------------- helpers ----------------
__device__ __forceinline__ uint32_t smem_u32(const void* p) {
    uint32_t a;
    asm("{ .reg .u64 t; cvta.to.shared.u64 t, %1; cvt.u32.u64 %0, t; }" : "=r"(a) : "l"(p));
    return a;
}
__device__ __forceinline__ void ldsm4(uint32_t* r, uint32_t addr) {
    asm volatile("ldmatrix.sync.aligned.m8n8.x4.shared.b16 {%0,%1,%2,%3}, [%4];"
        : "=r"(r[0]), "=r"(r[1]), "=r"(r[2]), "=r"(r[3]) : "r"(addr));
}
__device__ __forceinline__ void mma16816(float* c, const uint32_t* a, const uint32_t* b) {
    asm volatile("mma.sync.aligned.m16n8k16.row.col.f32.f16.f16.f32 "
        "{%0,%1,%2,%3}, {%4,%5,%6,%7}, {%8,%9}, {%0,%1,%2,%3};"
        : "+f"(c[0]), "+f"(c[1]), "+f"(c[2]), "+f"(c[3])
        : "r"(a[0]), "r"(a[1]), "r"(a[2]), "r"(a[3]), "r"(b[0]), "r"(b[1]));
}
__device__ __forceinline__ void hsplit(float v, uint16_t &h, uint16_t &l) {
    __half hh = __float2half_rn(v);
    h = __half_as_ushort(hh);
    l = __half_as_ushort(__float2half_rn(v - __half2float(hh)));
}
__device__ __forceinline__ uint32_t pack2h(float a, float b) {
    __half2 h = __floats2half2_rn(a, b);
    return *(uint32_t*)&h;
}

// ---------------- aux kernels ----------------
__global__ void zero_stats_k(int nTotal) {
    const int i = threadIdx.x;   // 512
    if (i < 256) ((float*)g_sums)[i] = 0.f;
    else ((float*)g_sumsq)[i - 256] = 0.f;
#pragma unroll
    for (int j = 0; j < 4; ++j) {
        ((uint32_t*)g_biasHi)[i + j * 512] = 0u;
        ((uint32_t*)g_biasLo)[i + j * 512] = 0u;
    }
    if (i < 32) ((uint32_t*)(g_fS + (size_t)nTotal * 64))[i] = 0u;
    else if (i < 64) ((uint32_t*)(g_aSa + (size_t)nTotal * 64))[i - 32] = 0u;
    else if (i < 96) ((uint32_t*)(g_aSb + (size_t)nTotal * 64))[i - 64] = 0u;
}

// Build one packed b16x2 frag reg from the scaled weight plane.
__device__ __forceinline__ uint32_t frag_reg(const float* __restrict__ src,
                                             const float* __restrict__ sck,
                                             int kk, int nn, int plane) {
    const float s0 = sck ? sck[kk] : 1.f;
    const float s1 = sck ? sck[kk + 1] : 1.f;
    uint16_t h0, l0, h1, l1;
    hsplit(src[kk * 64 + nn] * s0 * WSCALE, h0, l0);
    hsplit(src[(kk + 1) * 64 + nn] * s1 * WSCALE, h1, l1);
    const uint16_t a = plane ? l0 : h0;
    const uint16_t b = plane ? l1 : h1;
    return (uint32_t)a | ((uint32_t)b << 16);
}

__device__ __forceinline__ void write_frags(const float* __restrict__ src,
                                            const float* __restrict__ sck,
                                            __half* __restrict__ dstTap, int tid) {
#pragma unroll
    for (int i = 0; i < 4; ++i) {
        const int idx = tid + i * 256;           // 0..1023 uint4 slots
        const int lane = idx & 31;
        const int chunk = idx >> 5;              // 0..31: q*8 + wn*4 + c
        const int q = chunk >> 3, wn = (chunk >> 2) & 1, c = chunk & 3;
        const int plane = c >> 1, p = c & 1;
        const int m = lane & 3, nr = lane >> 2;
        const int k0 = 16 * q;
        const int n0 = wn * 32 + 16 * p + nr;
        uint4 o;
        o.x = frag_reg(src, sck, k0 + 2 * m,     n0,     plane);
        o.y = frag_reg(src, sck, k0 + 2 * m,     n0 + 8, plane);
        o.z = frag_reg(src, sck, k0 + 8 + 2 * m, n0,     plane);
        o.w = frag_reg(src, sck, k0 + 8 + 2 * m, n0 + 8, plane);
        ((uint4*)dstTap)[idx] = o;
    }
}

// plain weights [9][c][o] -> fragment layout (tensors 0 and 2)
__global__ void prep_plain_k(const float* __restrict__ w1, const float* __restrict__ w2) {
    const int t = (blockIdx.x < KTAPS) ? 0 : 2;
    const int k = blockIdx.x % KTAPS;
    const float* src = ((t == 0) ? w1 : w2) + k * 4096;
    __half* dst = g_wFrag + (size_t)t * FRAG_TENSOR_HALVES + (size_t)k * FRAG_TAP_HALVES;
    write_frags(src, nullptr, dst, threadIdx.x);
}

// fold BN(stage) into weights -> fragment layout; bias_k[o] = 256*sum_c shift[c]*W[c,o]
// merged: blocks 0..8 -> (wA, tensor1, stage0), blocks 9..17 -> (wB, tensor3, stage2)
__global__ void prep_fold2_k(const float* __restrict__ wA, const float* __restrict__ wB,
                             const float* __restrict__ gA, const float* __restrict__ bA,
                             const float* __restrict__ gB, const float* __restrict__ bB,
                             float invN) {
    __shared__ float sc[64], sh[64];
    const int sel = blockIdx.x / KTAPS;           // 0 or 1
    const int k = blockIdx.x % KTAPS, tid = threadIdx.x;
    const float* w = sel ? wB : wA;
    const float* gamma = sel ? gB : gA;
    const float* beta  = sel ? bB : bA;
    const int stage = sel ? 2 : 0;
    const int tensor = sel ? 3 : 1;
    if (tid < 64) {
        const float m = g_sums[stage][tid] * invN;
        const float v = g_sumsq[stage][tid] * invN - m * m;
        const float a = gamma[tid] * rsqrtf(v + EPS_BN);
        sc[tid] = a;
        sh[tid] = beta[tid] - m * a;
    }
    __syncthreads();
    const float* src = w + (size_t)k * 4096;
    __half* dst = g_wFrag + (size_t)tensor * FRAG_TENSOR_HALVES + (size_t)k * FRAG_TAP_HALVES;
    write_frags(src, sc, dst, tid);
    if (tid < 64) {
        float s = 0.f;
#pragma unroll 8
        for (int c = 0; c < 64; ++c) s += sh[c] * src[c * 64 + tid];
        uint16_t h, l;
        hsplit(s * WSCALE, h, l);
        g_biasHi[tensor * 1024 + tid * 16 + k] = __ushort_as_half(h);
        g_biasLo[tensor * 1024 + tid * 16 + k] = __ushort_as_half(l);
    }
}

// fp32 features -> fp16 rows (once)
__global__ __launch_bounds__(256)
void split_k(const float* __restrict__ src, __half* __restrict__ dst, int nTotal) {
    const int row = blockIdx.x * 256 + threadIdx.x;
    if (row >= nTotal) return;
    const float4* s = (const float4*)(src + (size_t)row * CCH);
    uint4* d = (uint4*)(dst + (size_t)row * 64);
#pragma unroll
    for (int g = 0; g < 8; ++g) {
        const float4 v0 = s[2 * g], v1 = s[2 * g + 1];
        uint4 o;
        o.x = pack2h(v0.x, v0.y);
        o.y = pack2h(v0.z, v0.w);
        o.z = pack2h(v1.x, v1.y);
        o.w = pack2h(v1.z, v1.w);
        d[g] = o;
    }
}

// ---------------- main conv kernel (fp16 2-term; paired taps, 1 sync / 2 taps) ----------------
template <bool HAS_BIAS, bool OUT_PLANES>
__global__ __launch_bounds__(NTHR, 3)
void conv_mma_k(const __half* __restrict__ src0, const __half* __restrict__ src1,
                const int* __restrict__ nbr0, const int* __restrict__ nbr1,
                int wt0, int wt1,
                float* __restrict__ dstF0, float* __restrict__ dstF1,
                __half* __restrict__ dstP0, __half* __restrict__ dstP1,
                int nTotal, int stage0, int stage1)
{
    extern __shared__ __align__(128) char smemc[];
    __shared__ uint4 sBBh[128];       // bias hi [64 o][16 taps] fp16
    __shared__ uint4 sBBl[128];
    __shared__ int   sNbr[128 * KTAPS];  // neighbor ids, all rows x taps

    const int sel = blockIdx.y;
    const __half* __restrict__ src = sel ? src1 : src0;
    const int*    __restrict__ nbr = sel ? nbr1 : nbr0;
    const int wtIdx = sel ? wt1 : wt0;
    float* __restrict__ dstF = sel ? dstF1 : dstF0;
    __half* __restrict__ dstP = sel ? dstP1 : dstP0;
    const int stage = sel ? stage1 : stage0;

    const int tid   = threadIdx.x;
    const int lane  = tid & 31;
    const int wid   = tid >> 5;
    const int nBase = blockIdx.x * TN;
    const bool rowOK = (nBase + tid) < nTotal;

    const uint32_t sbase = smem_u32(smemc);
    // 2M x 2N warp grid: warp tile = 64 rows x 32 outch
    const int wm = wid & 1, wn = wid >> 1;
    const int rowBase = wm * 64;
    const int colBase = wn * 32;
    const int lsw = lane & 7, l15 = lane & 15, l16 = lane >> 4;

    // neighbor table (coalesced fill; invalid rows -> pad index nTotal)
#pragma unroll
    for (int j = 0; j < KTAPS; ++j)
        sNbr[tid * KTAPS + j] = rowOK ? nbr[(size_t)(nBase + tid) * KTAPS + j] : nTotal;

    if (HAS_BIAS) {
        sBBh[tid] = ((const uint4*)(g_biasHi + wtIdx * 1024))[tid];
        sBBl[tid] = ((const uint4*)(g_biasLo + wtIdx * 1024))[tid];
    }

    float C[4][4][4];
#pragma unroll
    for (int mt = 0; mt < 4; ++mt)
#pragma unroll
        for (int nt = 0; nt < 4; ++nt)
#pragma unroll
            for (int i = 0; i < 4; ++i) C[mt][nt][i] = 0.f;

    // B fragments: [tap][q][wn][chunk][lane] uint4
    const uint4* bF = (const uint4*)(g_wFrag + (size_t)wtIdx * FRAG_TENSOR_HALVES) + lane;

    // cooperative gather: 8 lanes per row, 4 rows per instruction (full 128B lines)
    const int gRow0  = (wid << 5) + (lane >> 3);   // +4 per it
    const int gChunk = lane & 7;
    uint4 pa[8];

    // tap k lives at stage ((k>>1)&1), slot (k&1)
    auto tapAddr = [&](int k) -> uint32_t {
        return sbase + (uint32_t)(((k >> 1) & 1) * STAGE_BYTES + (k & 1) * TAP_BYTES);
    };

    auto ldgA = [&](int k) {
#pragma unroll
        for (int it = 0; it < 8; ++it) {
            const int rl = gRow0 + (it << 2);
            const int nidx = sNbr[rl * KTAPS + k];
            pa[it] = *(const uint4*)(src + (size_t)nidx * 64 + (gChunk << 3));
        }
    };
    auto stsA = [&](int k) {
        char* ab = smemc + (tapAddr(k) - sbase);
#pragma unroll
        for (int it = 0; it < 8; ++it) {
            const int rl = gRow0 + (it << 2);
            *(uint4*)(ab + rl * 128 + ((gChunk ^ (rl & 7)) << 4)) = pa[it];
        }
    };
    auto mmaTap = [&](int k) {
        const uint32_t ab = tapAddr(k);
#pragma unroll
        for (int q = 0; q < 4; ++q) {
            const int kg = 2 * q + l16;
            uint32_t a_[4][4];
#pragma unroll
            for (int mt = 0; mt < 4; ++mt) {
                const uint32_t off =
                    (uint32_t)((rowBase + mt * 16 + l15) * 128 + ((kg ^ lsw) << 4));
                ldsm4(a_[mt], ab + off);
            }
            // B fragments direct from gmem (L1-hot, fully coalesced)
            const uint4* bq = bF + (size_t)(((k * 4 + q) * 2 + wn) * 4) * 32;
            const uint4 f0 = bq[0], f1 = bq[32], f2 = bq[64], f3 = bq[96];
            uint32_t bh[4][2], bl[4][2];
            bh[0][0] = f0.x; bh[1][0] = f0.y; bh[0][1] = f0.z; bh[1][1] = f0.w;
            bh[2][0] = f1.x; bh[3][0] = f1.y; bh[2][1] = f1.z; bh[3][1] = f1.w;
            bl[0][0] = f2.x; bl[1][0] = f2.y; bl[0][1] = f2.z; bl[1][1] = f2.w;
            bl[2][0] = f3.x; bl[3][0] = f3.y; bl[2][1] = f3.z; bl[3][1] = f3.w;
#pragma unroll
            for (int mt = 0; mt < 4; ++mt)
#pragma unroll
                for (int nt = 0; nt < 4; ++nt) {
                    mma16816(C[mt][nt], a_[mt], bh[nt]);
                    mma16816(C[mt][nt], a_[mt], bl[nt]);
                }
        }
    };

    __syncthreads();                 // sNbr visible to all warps
    ldgA(0); stsA(0);
    ldgA(1); stsA(1);

#pragma unroll
    for (int it = 0; it < 5; ++it) {
        __syncthreads();             // pair (2it,2it+1) visible; stage (it+1)&1 free
        const int k0 = 2 * it, k1 = 2 * it + 1;

        if (k0 + 2 < KTAPS) ldgA(k0 + 2);   // latency hides under MMA(k0)
        mmaTap(k0);
        if (k0 + 2 < KTAPS) stsA(k0 + 2);

        if (k1 < KTAPS) {
            if (k1 + 2 < KTAPS) ldgA(k1 + 2);
            mmaTap(k1);
            if (k1 + 2 < KTAPS) stsA(k1 + 2);
        }
    }

    // ---- bias MMA: C += V(128x16) * B(16x64); V fragments built from sNbr ----
    if (HAS_BIAS) {
        uint32_t av[4][4];
        const int fr = lane >> 2, fc = (lane & 3) * 2;
#pragma unroll
        for (int mt = 0; mt < 4; ++mt) {
            const int r0 = rowBase + mt * 16 + fr;
            const int r1 = r0 + 8;
#pragma unroll
            for (int j = 0; j < 4; ++j) {
                const int rr = (j & 1) ? r1 : r0;
                const int c0 = fc + ((j >> 1) << 3);
                uint32_t lo = 0u, hi = 0u;
                if (c0     < KTAPS && sNbr[rr * KTAPS + c0]     < nTotal) lo = 0x3C00u;
                if (c0 + 1 < KTAPS && sNbr[rr * KTAPS + c0 + 1] < nTotal) hi = 0x3C00u;
                av[mt][j] = lo | (hi << 16);
            }
        }
        const uint32_t bhb = smem_u32(sBBh);
        const uint32_t blb = smem_u32(sBBl);
        uint32_t bbh[4][2], bbl[4][2];
#pragma unroll
        for (int p = 0; p < 2; ++p) {
            const uint32_t off = (uint32_t)((colBase + 16 * p + l15) * 32 + l16 * 16);
            uint32_t r[4];
            ldsm4(r, bhb + off);
            bbh[2*p][0] = r[0]; bbh[2*p+1][0] = r[1];
            bbh[2*p][1] = r[2]; bbh[2*p+1][1] = r[3];
            ldsm4(r, blb + off);
            bbl[2*p][0] = r[0]; bbl[2*p+1][0] = r[1];
            bbl[2*p][1] = r[2]; bbl[2*p+1][1] = r[3];
        }
#pragma unroll
        for (int mt = 0; mt < 4; ++mt)
#pragma unroll
            for (int nt = 0; nt < 4; ++nt) {
                mma16816(C[mt][nt], av[mt], bbh[nt]);
                mma16816(C[mt][nt], av[mt], bbl[nt]);
            }
    }

    // ---- epilogue: descale + leaky -> smem fp32 tile -> store + stats ----
    __syncthreads();
    float* sC = (float*)smemc;                   // [128][SC_STRIDE] = 34816B
    const int fg = lane >> 2, ft2 = (lane & 3) * 2;
#pragma unroll
    for (int mt = 0; mt < 4; ++mt)
#pragma unroll
        for (int nt = 0; nt < 4; ++nt) {
            float* c = C[mt][nt];
#pragma unroll
            for (int i = 0; i < 4; ++i) {
                const float v = c[i] * INV_WSCALE;
                c[i] = (v > 0.f) ? v : LEAK * v;
            }
            const int r0 = rowBase + mt * 16 + fg;
            const int col = colBase + nt * 8 + ft2;
            *(float2*)&sC[r0 * SC_STRIDE + col]       = make_float2(c[0], c[1]);
            *(float2*)&sC[(r0 + 8) * SC_STRIDE + col] = make_float2(c[2], c[3]);
        }
    __syncthreads();

    if (rowOK) {
        const float4* rowp = (const float4*)(sC + tid * SC_STRIDE);
        if (OUT_PLANES) {
            uint4* d = (uint4*)(dstP + (size_t)(nBase + tid) * 64);
#pragma unroll
            for (int g = 0; g < 8; ++g) {
                const float4 v0 = rowp[2 * g], v1 = rowp[2 * g + 1];
                uint4 o;
                o.x = pack2h(v0.x, v0.y);
                o.y = pack2h(v0.z, v0.w);
                o.z = pack2h(v1.x, v1.y);
                o.w = pack2h(v1.z, v1.w);
                d[g] = o;
            }
        } else {
            float4* drow = (float4*)(dstF + (size_t)(nBase + tid) * CCH);
#pragma unroll
            for (int c4 = 0; c4 < 16; ++c4) drow[c4] = rowp[c4];
        }
    }

    {
        const int ch = tid >> 1, half = tid & 1;
        float s = 0.f, s2 = 0.f;
#pragma unroll 8
        for (int i = 0; i < 64; ++i) {
            const float v = sC[(half * 64 + i) * SC_STRIDE + ch];
            s += v; s2 += v * v;
        }
        s  += __shfl_xor_sync(0xffffffffu, s, 1);
        s2 += __shfl_xor_sync(0xffffffffu, s2, 1);
        if (!half) {
            atomicAdd(&g_sums[stage][ch], s);
            atomicAdd(&g_sumsq[stage][ch], s2);
        }
    }
}

// out = BN3(out) + BN1(y2); coefficients for stages 1,3 computed inline
__global__ __launch_bounds__(256)
void final_k(float* __restrict__ out, const float* __restrict__ y2,
             const float* __restrict__ g1_, const float* __restrict__ b1_,
             const float* __restrict__ g3_, const float* __restrict__ b3_,
             float invN, int total4)
{
    __shared__ float c1[64], s1[64], c3[64], s3[64];
    const int tid = threadIdx.x;
    if (tid < 64) {
        const float m1 = g_sums[1][tid] * invN;
        const float v1 = g_sumsq[1][tid] * invN - m1 * m1;
        const float a1 = g1_[tid] * rsqrtf(v1 + EPS_BN);
        c1[tid] = a1; s1[tid] = b1_[tid] - m1 * a1;
        const float m3 = g_sums[3][tid] * invN;
        const float v3 = g_sumsq[3][tid] * invN - m3 * m3;
        const float a3 = g3_[tid] * rsqrtf(v3 + EPS_BN);
        c3[tid] = a3; s3[tid] = b3_[tid] - m3 * a3;
    }
    __syncthreads();
    const int i = blockIdx.x * 256 + tid;
    if (i >= total4) return;
    float4 a = ((float4*)out)[i];
    const float4 b = ((const float4*)y2)[i];
    const int c = (i * 4) & 63;
    a.x = fmaf(a.x, c3[c + 0], s3[c + 0]) + fmaf(b.x, c1[c + 0], s1[c + 0]);
    a.y = fmaf(a.y, c3[c + 1], s3[c + 1]) + fmaf(b.y, c1[c + 1], s1[c + 1]);
    a.z = fmaf(a.z, c3[c + 2], s3[c + 2]) + fmaf(b.z, c1[c + 2], s1[c + 2]);
    a.w = fmaf(a.w, c3[c + 3], s3[c + 3]) + fmaf(b.w, c1[c + 3], s1[c + 3]);
    ((float4*)out)[i] = a;
}

// ---------------- launcher ----------------
extern "C" void kernel_launch(void* const* d_in, const int* in_sizes, int n_in,
                              void* d_out, int out_size)
{
    const float* features = (const float*)d_in[0];
    const float* w1   = (const float*)d_in[1];
    const float* w1_2 = (const float*)d_in[2];
    const float* w2   = (const float*)d_in[3];
    const float* w3   = (const float*)d_in[4];
    const float* g0   = (const float*)d_in[5];
    const float* b0   = (const float*)d_in[6];
    const float* g0_2 = (const float*)d_in[7];
    const float* b0_2 = (const float*)d_in[8];
    const float* g1   = (const float*)d_in[9];
    const float* b1   = (const float*)d_in[10];
    const float* g2   = (const float*)d_in[11];
    const float* b2   = (const float*)d_in[12];
    const int*   nbr13 = (const int*)d_in[13];
    const int*   nbr31 = (const int*)d_in[14];

    const int nTotal = in_sizes[0] / CCH;
    const float invN = 1.0f / (float)nTotal;
    const int grid   = (nTotal + TN - 1) / TN;
    const int gridS  = (nTotal + 255) / 256;

    cudaFuncSetAttribute(conv_mma_k<false, true>,
                         cudaFuncAttributeMaxDynamicSharedMemorySize, DSM_BYTES);
    cudaFuncSetAttribute(conv_mma_k<true, false>,
                         cudaFuncAttributeMaxDynamicSharedMemorySize, DSM_BYTES);

    float* bufB = nullptr;
    __half *fS = nullptr, *aSa = nullptr, *aSb = nullptr;
    cudaGetSymbolAddress((void**)&bufB, g_bufB);
    cudaGetSymbolAddress((void**)&fS,  g_fS);
    cudaGetSymbolAddress((void**)&aSa, g_aSa);
    cudaGetSymbolAddress((void**)&aSb, g_aSb);
    float* out = (float*)d_out;

    zero_stats_k<<<1, 512>>>(nTotal);
    prep_plain_k<<<2 * KTAPS, 256>>>(w1, w2);
    split_k<<<gridS, 256>>>(features, fS, nTotal);

    // phase A: conv0 (shortcut, nbr13, w1 -> aSa, stats0) || conv2 (main, nbr31, w2 -> aSb, stats2)
    {
        dim3 g2d(grid, 2);
        conv_mma_k<false, true><<<g2d, NTHR, DSM_BYTES>>>(
            fS, fS, nbr13, nbr31, 0, 2,
            nullptr, nullptr, aSa, aSb, nTotal, 0, 2);
    }

    // fold BN0 into w1_2 (tensor1) and BN2 into w3 (tensor3), one launch
    prep_fold2_k<<<2 * KTAPS, 256>>>(w1_2, w3, g0, b0, g1, b1, invN);

    // phase B: conv1 (aSa, nbr31, w1_2 -> bufB, stats1) || conv3 (aSb, nbr13, w3 -> out, stats3)
    {
        dim3 g2d(grid, 2);
        conv_mma_k<true, false><<<g2d, NTHR, DSM_BYTES>>>(
            aSa, aSb, nbr31, nbr13, 1, 3,
            bufB, out, nullptr, nullptr, nTotal, 1, 3);
    }

    // out = BN3(out) + BN1(bufB)
    const int total4 = nTotal * CCH / 4;
    final_k<<<(total4 + 255) / 256, 256>>>(out, bufB, g0_2, b0_2, g2, b2, invN, total4);
}

// round 15
// speedup vs baseline: 3.5544x; 1.0323x over previous
#include <cuda_runtime.h>
#include <cuda_fp16.h>
#include <cstdint>

// ---------------- problem constants ----------------
#define NMAX   200000
#define CCH    64
#define KTAPS  9
#define TN     128          // rows per block (MMA M)
#define NTHR   128
#define LEAK   0.01f
#define EPS_BN 1e-5f
#define WSCALE 256.0f       // weight scaling (keeps fp16 lo-plane normal)
#define INV_WSCALE (1.0f / 256.0f)

// dynamic smem: 2 stages x 32K (2 taps per stage) / fp32 epilogue tile 34816B
#define TAP_BYTES   16384
#define STAGE_BYTES 32768
#define DSM_BYTES   65536
#define SC_STRIDE 68        // epilogue fp32 tile stride (floats)

// B fragment layout: halves per tap = 4q * (2wn*4c) chunks * 32 lanes * 8 = 8192
#define FRAG_TAP_HALVES   8192
#define FRAG_TENSOR_HALVES (KTAPS * FRAG_TAP_HALVES)   // 73728

// ---------------- scratch (no cudaMalloc allowed) ----------------
// fp16 feature rows: [row][64 fp16]; row nTotal = zero pad
__device__ __half g_fS [((size_t)NMAX + 1) * 64];
__device__ __half g_aSa[((size_t)NMAX + 1) * 64];   // shortcut branch planes
__device__ __half g_aSb[((size_t)NMAX + 1) * 64];   // main branch planes
__device__ __half g_y2h[(size_t)NMAX * 64];         // y2 (shortcut output) fp16
__device__ __half g_wFrag[4 * FRAG_TENSOR_HALVES];  // B in per-lane MMA fragment layout
__device__ __half g_biasHi[4 * 64 * 16];            // [tensor][o*16 + tap], x256
__device__ __half g_biasLo[4 * 64 * 16];
__device__ float g_sums [4][CCH];
__device__ float g_sumsq[4][CCH];

// ---------------- helpers ----------------
__device__ __forceinline__ uint32_t smem_u32(const void* p) {
    uint32_t a;
    asm("{ .reg .u64 t; cvta.to.shared.u64 t, %1; cvt.u32.u64 %0, t; }" : "=r"(a) : "l"(p));
    return a;
}
__device__ __forceinline__ void ldsm4(uint32_t* r, uint32_t addr) {
    asm volatile("ldmatrix.sync.aligned.m8n8.x4.shared.b16 {%0,%1,%2,%3}, [%4];"
        : "=r"(r[0]), "=r"(r[1]), "=r"(r[2]), "=r"(r[3]) : "r"(addr));
}
__device__ __forceinline__ void mma16816(float* c, const uint32_t* a, const uint32_t* b) {
    asm volatile("mma.sync.aligned.m16n8k16.row.col.f32.f16.f16.f32 "
        "{%0,%1,%2,%3}, {%4,%5,%6,%7}, {%8,%9}, {%0,%1,%2,%3};"
        : "+f"(c[0]), "+f"(c[1]), "+f"(c[2]), "+f"(c[3])
        : "r"(a[0]), "r"(a[1]), "r"(a[2]), "r"(a[3]), "r"(b[0]), "r"(b[1]));
}
__device__ __forceinline__ void hsplit(float v, uint16_t &h, uint16_t &l) {
    __half hh = __float2half_rn(v);
    h = __half_as_ushort(hh);
    l = __half_as_ushort(__float2half_rn(v - __half2float(hh)));
}
__device__ __forceinline__ uint32_t pack2h(float a, float b) {
    __half2 h = __floats2half2_rn(a, b);
    return *(uint32_t*)&h;
}

// Build one packed b16x2 frag reg from the scaled weight plane.
__device__ __forceinline__ uint32_t frag_reg(const float* __restrict__ src,
                                             const float* __restrict__ sck,
                                             int kk, int nn, int plane) {
    const float s0 = sck ? sck[kk] : 1.f;
    const float s1 = sck ? sck[kk + 1] : 1.f;
    uint16_t h0, l0, h1, l1;
    hsplit(src[kk * 64 + nn] * s0 * WSCALE, h0, l0);
    hsplit(src[(kk + 1) * 64 + nn] * s1 * WSCALE, h1, l1);
    const uint16_t a = plane ? l0 : h0;
    const uint16_t b = plane ? l1 : h1;
    return (uint32_t)a | ((uint32_t)b << 16);
}

__device__ __forceinline__ void write_frags(const float* __restrict__ src,
                                            const float* __restrict__ sck,
                                            __half* __restrict__ dstTap, int tid) {
#pragma unroll
    for (int i = 0; i < 4; ++i) {
        const int idx = tid + i * 256;           // 0..1023 uint4 slots
        const int lane = idx & 31;
        const int chunk = idx >> 5;              // 0..31: q*8 + wn*4 + c
        const int q = chunk >> 3, wn = (chunk >> 2) & 1, c = chunk & 3;
        const int plane = c >> 1, p = c & 1;
        const int m = lane & 3, nr = lane >> 2;
        const int k0 = 16 * q;
        const int n0 = wn * 32 + 16 * p + nr;
        uint4 o;
        o.x = frag_reg(src, sck, k0 + 2 * m,     n0,     plane);
        o.y = frag_reg(src, sck, k0 + 2 * m,     n0 + 8, plane);
        o.z = frag_reg(src, sck, k0 + 8 + 2 * m, n0,     plane);
        o.w = frag_reg(src, sck, k0 + 8 + 2 * m, n0 + 8, plane);
        ((uint4*)dstTap)[idx] = o;
    }
}

// ---------------- merged preamble: split + prep_plain + zero (one launch) ----------------
// blocks [0, gridS): feature split; [gridS, gridS+18): weight frags; gridS+18: zero
__global__ __launch_bounds__(256)
void pre_k(const float* __restrict__ features,
           const float* __restrict__ w1, const float* __restrict__ w2,
           int nTotal, int gridS)
{
    const int bid = blockIdx.x, tid = threadIdx.x;
    if (bid < gridS) {
        const int row = bid * 256 + tid;
        if (row >= nTotal) return;
        const float4* s = (const float4*)(features + (size_t)row * CCH);
        uint4* d = (uint4*)(g_fS + (size_t)row * 64);
#pragma unroll
        for (int g = 0; g < 8; ++g) {
            const float4 v0 = s[2 * g], v1 = s[2 * g + 1];
            uint4 o;
            o.x = pack2h(v0.x, v0.y);
            o.y = pack2h(v0.z, v0.w);
            o.z = pack2h(v1.x, v1.y);
            o.w = pack2h(v1.z, v1.w);
            d[g] = o;
        }
        return;
    }
    const int j = bid - gridS;
    if (j < 2 * KTAPS) {
        const int t = (j < KTAPS) ? 0 : 2;
        const int k = j % KTAPS;
        const float* src = ((t == 0) ? w1 : w2) + k * 4096;
        __half* dst = g_wFrag + (size_t)t * FRAG_TENSOR_HALVES + (size_t)k * FRAG_TAP_HALVES;
        write_frags(src, nullptr, dst, tid);
        return;
    }
    // zero block
    ((float*)g_sums)[tid]  = 0.f;
    ((float*)g_sumsq)[tid] = 0.f;
#pragma unroll
    for (int r = 0; r < 8; ++r) {
        ((uint32_t*)g_biasHi)[tid + r * 256] = 0u;
        ((uint32_t*)g_biasLo)[tid + r * 256] = 0u;
    }
    if (tid < 32) ((uint32_t*)(g_fS + (size_t)nTotal * 64))[tid] = 0u;
    else if (tid < 64) ((uint32_t*)(g_aSa + (size_t)nTotal * 64))[tid - 32] = 0u;
    else if (tid < 96) ((uint32_t*)(g_aSb + (size_t)nTotal * 64))[tid - 64] = 0u;
}

// fold BN(stage) into weights -> fragment layout; bias_k[o] = 256*sum_c shift[c]*W[c,o]
// merged: blocks 0..8 -> (wA, tensor1, stage0), blocks 9..17 -> (wB, tensor3, stage2)
__global__ void prep_fold2_k(const float* __restrict__ wA, const float* __restrict__ wB,
                             const float* __restrict__ gA, const float* __restrict__ bA,
                             const float* __restrict__ gB, const float* __restrict__ bB,
                             float invN) {
    __shared__ float sc[64], sh[64];
    const int sel = blockIdx.x / KTAPS;           // 0 or 1
    const int k = blockIdx.x % KTAPS, tid = threadIdx.x;
    const float* w = sel ? wB : wA;
    const float* gamma = sel ? gB : gA;
    const float* beta  = sel ? bB : bA;
    const int stage = sel ? 2 : 0;
    const int tensor = sel ? 3 : 1;
    if (tid < 64) {
        const float m = g_sums[stage][tid] * invN;
        const float v = g_sumsq[stage][tid] * invN - m * m;
        const float a = gamma[tid] * rsqrtf(v + EPS_BN);
        sc[tid] = a;
        sh[tid] = beta[tid] - m * a;
    }
    __syncthreads();
    const float* src = w + (size_t)k * 4096;
    __half* dst = g_wFrag + (size_t)tensor * FRAG_TENSOR_HALVES + (size_t)k * FRAG_TAP_HALVES;
    write_frags(src, sc, dst, tid);
    if (tid < 64) {
        float s = 0.f;
#pragma unroll 8
        for (int c = 0; c < 64; ++c) s += sh[c] * src[c * 64 + tid];
        uint16_t h, l;
        hsplit(s * WSCALE, h, l);
        g_biasHi[tensor * 1024 + tid * 16 + k] = __ushort_as_half(h);
        g_biasLo[tensor * 1024 + tid * 16 + k] = __ushort_as_half(l);
    }
}

// ---------------- main conv kernel (fp16 2-term; paired taps, 1 sync / 2 taps) ----------------
// outMode: 0 = fp32 rows (dstF), 1 = hi/lo planes (dstP), 2 = fp16 rows (dstH)
template <bool HAS_BIAS>
__global__ __launch_bounds__(NTHR, 3)
void conv_mma_k(const __half* __restrict__ src0, const __half* __restrict__ src1,
                const int* __restrict__ nbr0, const int* __restrict__ nbr1,
                int wt0, int wt1,
                float* __restrict__ dstF0, float* __restrict__ dstF1,
                __half* __restrict__ dstH0, __half* __restrict__ dstH1,
                int om0, int om1,
                int nTotal, int stage0, int stage1)
{
    extern __shared__ __align__(128) char smemc[];
    __shared__ uint4 sBBh[128];       // bias hi [64 o][16 taps] fp16
    __shared__ uint4 sBBl[128];
    __shared__ int   sNbr[128 * KTAPS];  // neighbor ids, all rows x taps

    const int sel = blockIdx.y;
    const __half* __restrict__ src = sel ? src1 : src0;
    const int*    __restrict__ nbr = sel ? nbr1 : nbr0;
    const int wtIdx = sel ? wt1 : wt0;
    float*  __restrict__ dstF = sel ? dstF1 : dstF0;
    __half* __restrict__ dstH = sel ? dstH1 : dstH0;
    const int outMode = sel ? om1 : om0;
    const int stage = sel ? stage1 : stage0;

    const int tid   = threadIdx.x;
    const int lane  = tid & 31;
    const int wid   = tid >> 5;
    const int nBase = blockIdx.x * TN;
    const bool rowOK = (nBase + tid) < nTotal;

    const uint32_t sbase = smem_u32(smemc);
    // 2M x 2N warp grid: warp tile = 64 rows x 32 outch
    const int wm = wid & 1, wn = wid >> 1;
    const int rowBase = wm * 64;
    const int colBase = wn * 32;
    const int lsw = lane & 7, l15 = lane & 15, l16 = lane >> 4;

    // neighbor table (coalesced fill; invalid rows -> pad index nTotal)
#pragma unroll
    for (int j = 0; j < KTAPS; ++j)
        sNbr[tid * KTAPS + j] = rowOK ? nbr[(size_t)(nBase + tid) * KTAPS + j] : nTotal;

    if (HAS_BIAS) {
        sBBh[tid] = ((const uint4*)(g_biasHi + wtIdx * 1024))[tid];
        sBBl[tid] = ((const uint4*)(g_biasLo + wtIdx * 1024))[tid];
    }

    float C[4][4][4];
#pragma unroll
    for (int mt = 0; mt < 4; ++mt)
#pragma unroll
        for (int nt = 0; nt < 4; ++nt)
#pragma unroll
            for (int i = 0; i < 4; ++i) C[mt][nt][i] = 0.f;

    // B fragments: [tap][q][wn][chunk][lane] uint4
    const uint4* bF = (const uint4*)(g_wFrag + (size_t)wtIdx * FRAG_TENSOR_HALVES) + lane;

    // cooperative gather: 8 lanes per row, 4 rows per instruction (full 128B lines)
    const int gRow0  = (wid << 5) + (lane >> 3);   // +4 per it
    const int gChunk = lane & 7;
    uint4 pa[8];

    // tap k lives at stage ((k>>1)&1), slot (k&1)
    auto tapAddr = [&](int k) -> uint32_t {
        return sbase + (uint32_t)(((k >> 1) & 1) * STAGE_BYTES + (k & 1) * TAP_BYTES);
    };

    auto ldgA = [&](int k) {
#pragma unroll
        for (int it = 0; it < 8; ++it) {
            const int rl = gRow0 + (it << 2);
            const int nidx = sNbr[rl * KTAPS + k];
            pa[it] = *(const uint4*)(src + (size_t)nidx * 64 + (gChunk << 3));
        }
    };
    auto stsA = [&](int k) {
        char* ab = smemc + (tapAddr(k) - sbase);
#pragma unroll
        for (int it = 0; it < 8; ++it) {
            const int rl = gRow0 + (it << 2);
            *(uint4*)(ab + rl * 128 + ((gChunk ^ (rl & 7)) << 4)) = pa[it];
        }
    };
    auto mmaTap = [&](int k) {
        const uint32_t ab = tapAddr(k);
#pragma unroll
        for (int q = 0; q < 4; ++q) {
            const int kg = 2 * q + l16;
            uint32_t a_[4][4];
#pragma unroll
            for (int mt = 0; mt < 4; ++mt) {
                const uint32_t off =
                    (uint32_t)((rowBase + mt * 16 + l15) * 128 + ((kg ^ lsw) << 4));
                ldsm4(a_[mt], ab + off);
            }
            // B fragments direct from gmem (L1-hot, fully coalesced)
            const uint4* bq = bF + (size_t)(((k * 4 + q) * 2 + wn) * 4) * 32;
            const uint4 f0 = bq[0], f1 = bq[32], f2 = bq[64], f3 = bq[96];
            uint32_t bh[4][2], bl[4][2];
            bh[0][0] = f0.x; bh[1][0] = f0.y; bh[0][1] = f0.z; bh[1][1] = f0.w;
            bh[2][0] = f1.x; bh[3][0] = f1.y; bh[2][1] = f1.z; bh[3][1] = f1.w;
            bl[0][0] = f2.x; bl[1][0] = f2.y; bl[0][1] = f2.z; bl[1][1] = f2.w;
            bl[2][0] = f3.x; bl[3][0] = f3.y; bl[2][1] = f3.z; bl[3][1] = f3.w;
#pragma unroll
            for (int mt = 0; mt < 4; ++mt)
#pragma unroll
                for (int nt = 0; nt < 4; ++nt) {
                    mma16816(C[mt][nt], a_[mt], bh[nt]);
                    mma16816(C[mt][nt], a_[mt], bl[nt]);
                }
        }
    };

    __syncthreads();                 // sNbr visible to all warps
    ldgA(0); stsA(0);
    ldgA(1); stsA(1);

#pragma unroll
    for (int it = 0; it < 5; ++it) {
        __syncthreads();             // pair (2it,2it+1) visible; stage (it+1)&1 free
        const int k0 = 2 * it, k1 = 2 * it + 1;

        if (k0 + 2 < KTAPS) ldgA(k0 + 2);   // latency hides under MMA(k0)
        mmaTap(k0);
        if (k0 + 2 < KTAPS) stsA(k0 + 2);

        if (k1 < KTAPS) {
            if (k1 + 2 < KTAPS) ldgA(k1 + 2);
            mmaTap(k1);
            if (k1 + 2 < KTAPS) stsA(k1 + 2);
        }
    }

    // ---- bias MMA: C += V(128x16) * B(16x64); V fragments built from sNbr ----
    if (HAS_BIAS) {
        uint32_t av[4][4];
        const int fr = lane >> 2, fc = (lane & 3) * 2;
#pragma unroll
        for (int mt = 0; mt < 4; ++mt) {
            const int r0 = rowBase + mt * 16 + fr;
            const int r1 = r0 + 8;
#pragma unroll
            for (int j = 0; j < 4; ++j) {
                const int rr = (j & 1) ? r1 : r0;
                const int c0 = fc + ((j >> 1) << 3);
                uint32_t lo = 0u, hi = 0u;
                if (c0     < KTAPS && sNbr[rr * KTAPS + c0]     < nTotal) lo = 0x3C00u;
                if (c0 + 1 < KTAPS && sNbr[rr * KTAPS + c0 + 1] < nTotal) hi = 0x3C00u;
                av[mt][j] = lo | (hi << 16);
            }
        }
        const uint32_t bhb = smem_u32(sBBh);
        const uint32_t blb = smem_u32(sBBl);
        uint32_t bbh[4][2], bbl[4][2];
#pragma unroll
        for (int p = 0; p < 2; ++p) {
            const uint32_t off = (uint32_t)((colBase + 16 * p + l15) * 32 + l16 * 16);
            uint32_t r[4];
            ldsm4(r, bhb + off);
            bbh[2*p][0] = r[0]; bbh[2*p+1][0] = r[1];
            bbh[2*p][1] = r[2]; bbh[2*p+1][1] = r[3];
            ldsm4(r, blb + off);
            bbl[2*p][0] = r[0]; bbl[2*p+1][0] = r[1];
            bbl[2*p][1] = r[2]; bbl[2*p+1][1] = r[3];
        }
#pragma unroll
        for (int mt = 0; mt < 4; ++mt)
#pragma unroll
            for (int nt = 0; nt < 4; ++nt) {
                mma16816(C[mt][nt], av[mt], bbh[nt]);
                mma16816(C[mt][nt], av[mt], bbl[nt]);
            }
    }

    // ---- epilogue: descale + leaky -> smem fp32 tile -> store + stats ----
    __syncthreads();
    float* sC = (float*)smemc;                   // [128][SC_STRIDE] = 34816B
    const int fg = lane >> 2, ft2 = (lane & 3) * 2;
#pragma unroll
    for (int mt = 0; mt < 4; ++mt)
#pragma unroll
        for (int nt = 0; nt < 4; ++nt) {
            float* c = C[mt][nt];
#pragma unroll
            for (int i = 0; i < 4; ++i) {
                const float v = c[i] * INV_WSCALE;
                c[i] = (v > 0.f) ? v : LEAK * v;
            }
            const int r0 = rowBase + mt * 16 + fg;
            const int col = colBase + nt * 8 + ft2;
            *(float2*)&sC[r0 * SC_STRIDE + col]       = make_float2(c[0], c[1]);
            *(float2*)&sC[(r0 + 8) * SC_STRIDE + col] = make_float2(c[2], c[3]);
        }
    __syncthreads();

    if (rowOK) {
        const float4* rowp = (const float4*)(sC + tid * SC_STRIDE);
        if (outMode == 1) {          // hi/lo planes (feeds next conv)
            uint4* d = (uint4*)(dstH + (size_t)(nBase + tid) * 64);
            uint4 H[4], L[4];   // actually planes: need hi|lo split rows
            // planes layout: [row][hi 64 | lo 64]? NO — planes format here is
            // single fp16 row per plane-pair; reconstruct exactly as before:
            (void)H; (void)L;
            uint4* dp = (uint4*)(dstH + (size_t)(nBase + tid) * 64);
#pragma unroll
            for (int g = 0; g < 8; ++g) {
                const float4 v0 = rowp[2 * g], v1 = rowp[2 * g + 1];
                uint4 o;
                o.x = pack2h(v0.x, v0.y);
                o.y = pack2h(v0.z, v0.w);
                o.z = pack2h(v1.x, v1.y);
                o.w = pack2h(v1.z, v1.w);
                dp[g] = o;
            }
            (void)d;
        } else if (outMode == 2) {   // fp16 rows (y2 for final)
            uint4* d = (uint4*)(dstH + (size_t)(nBase + tid) * 64);
#pragma unroll
            for (int g = 0; g < 8; ++g) {
                const float4 v0 = rowp[2 * g], v1 = rowp[2 * g + 1];
                uint4 o;
                o.x = pack2h(v0.x, v0.y);
                o.y = pack2h(v0.z, v0.w);
                o.z = pack2h(v1.x, v1.y);
                o.w = pack2h(v1.z, v1.w);
                d[g] = o;
            }
        } else {                     // fp32 rows
            float4* drow = (float4*)(dstF + (size_t)(nBase + tid) * CCH);
#pragma unroll
            for (int c4 = 0; c4 < 16; ++c4) drow[c4] = rowp[c4];
        }
    }

    {
        const int ch = tid >> 1, half = tid & 1;
        float s = 0.f, s2 = 0.f;
#pragma unroll 8
        for (int i = 0; i < 64; ++i) {
            const float v = sC[(half * 64 + i) * SC_STRIDE + ch];
            s += v; s2 += v * v;
        }
        s  += __shfl_xor_sync(0xffffffffu, s, 1);
        s2 += __shfl_xor_sync(0xffffffffu, s2, 1);
        if (!half) {
            atomicAdd(&g_sums[stage][ch], s);
            atomicAdd(&g_sumsq[stage][ch], s2);
        }
    }
}

// out = BN3(out) + BN1(y2h); coefficients for stages 1,3 computed inline
__global__ __launch_bounds__(256)
void final_k(float* __restrict__ out, const __half* __restrict__ y2h,
             const float* __restrict__ g1_, const float* __restrict__ b1_,
             const float* __restrict__ g3_, const float* __restrict__ b3_,
             float invN, int total4)
{
    __shared__ float c1[64], s1[64], c3[64], s3[64];
    const int tid = threadIdx.x;
    if (tid < 64) {
        const float m1 = g_sums[1][tid] * invN;
        const float v1 = g_sumsq[1][tid] * invN - m1 * m1;
        const float a1 = g1_[tid] * rsqrtf(v1 + EPS_BN);
        c1[tid] = a1; s1[tid] = b1_[tid] - m1 * a1;
        const float m3 = g_sums[3][tid] * invN;
        const float v3 = g_sumsq[3][tid] * invN - m3 * m3;
        const float a3 = g3_[tid] * rsqrtf(v3 + EPS_BN);
        c3[tid] = a3; s3[tid] = b3_[tid] - m3 * a3;
    }
    __syncthreads();
    const int i = blockIdx.x * 256 + tid;
    if (i >= total4) return;
    float4 a = ((float4*)out)[i];
    const uint2 hb = ((const uint2*)y2h)[i];
    const __half2 p0 = *(const __half2*)&hb.x;
    const __half2 p1 = *(const __half2*)&hb.y;
    const float bx = __low2float(p0), by = __high2float(p0);
    const float bz = __low2float(p1), bw = __high2float(p1);
    const int c = (i * 4) & 63;
    a.x = fmaf(a.x, c3[c + 0], s3[c + 0]) + fmaf(bx, c1[c + 0], s1[c + 0]);
    a.y = fmaf(a.y, c3[c + 1], s3[c + 1]) + fmaf(by, c1[c + 1], s1[c + 1]);
    a.z = fmaf(a.z, c3[c + 2], s3[c + 2]) + fmaf(bz, c1[c + 2], s1[c + 2]);
    a.w = fmaf(a.w, c3[c + 3], s3[c + 3]) + fmaf(bw, c1[c + 3], s1[c + 3]);
    ((float4*)out)[i] = a;
}

// ---------------- launcher ----------------
extern "C" void kernel_launch(void* const* d_in, const int* in_sizes, int n_in,
                              void* d_out, int out_size)
{
    const float* features = (const float*)d_in[0];
    const float* w1   = (const float*)d_in[1];
    const float* w1_2 = (const float*)d_in[2];
    const float* w2   = (const float*)d_in[3];
    const float* w3   = (const float*)d_in[4];
    const float* g0   = (const float*)d_in[5];
    const float* b0   = (const float*)d_in[6];
    const float* g0_2 = (const float*)d_in[7];
    const float* b0_2 = (const float*)d_in[8];
    const float* g1   = (const float*)d_in[9];
    const float* b1   = (const float*)d_in[10];
    const float* g2   = (const float*)d_in[11];
    const float* b2   = (const float*)d_in[12];
    const int*   nbr13 = (const int*)d_in[13];
    const int*   nbr31 = (const int*)d_in[14];

    const int nTotal = in_sizes[0] / CCH;
    const float invN = 1.0f / (float)nTotal;
    const int grid   = (nTotal + TN - 1) / TN;
    const int gridS  = (nTotal + 255) / 256;

    cudaFuncSetAttribute(conv_mma_k<false>,
                         cudaFuncAttributeMaxDynamicSharedMemorySize, DSM_BYTES);
    cudaFuncSetAttribute(conv_mma_k<true>,
                         cudaFuncAttributeMaxDynamicSharedMemorySize, DSM_BYTES);

    __half *fS = nullptr, *aSa = nullptr, *aSb = nullptr, *y2h = nullptr;
    cudaGetSymbolAddress((void**)&fS,  g_fS);
    cudaGetSymbolAddress((void**)&aSa, g_aSa);
    cudaGetSymbolAddress((void**)&aSb, g_aSb);
    cudaGetSymbolAddress((void**)&y2h, g_y2h);
    float* out = (float*)d_out;

    // merged preamble: split + weight frags + zeroing (one launch)
    pre_k<<<gridS + 2 * KTAPS + 1, 256>>>(features, w1, w2, nTotal, gridS);

    // phase A: conv0 (shortcut, nbr13, w1 -> aSa planes, stats0)
    //        || conv2 (main, nbr31, w2 -> aSb planes, stats2)
    {
        dim3 g2d(grid, 2);
        conv_mma_k<false><<<g2d, NTHR, DSM_BYTES>>>(
            fS, fS, nbr13, nbr31, 0, 2,
            nullptr, nullptr, aSa, aSb, 1, 1, nTotal, 0, 2);
    }

    // fold BN0 into w1_2 (tensor1) and BN2 into w3 (tensor3), one launch
    prep_fold2_k<<<2 * KTAPS, 256>>>(w1_2, w3, g0, b0, g1, b1, invN);

    // phase B: conv1 (aSa, nbr31, w1_2 -> y2h fp16, stats1)
    //        || conv3 (aSb, nbr13, w3 -> out fp32, stats3)
    {
        dim3 g2d(grid, 2);
        conv_mma_k<true><<<g2d, NTHR, DSM_BYTES>>>(
            aSa, aSb, nbr31, nbr13, 1, 3,
            nullptr, out, y2h, nullptr, 2, 0, nTotal, 1, 3);
    }

    // out = BN3(out) + BN1(y2h)
    const int total4 = nTotal * CCH / 4;
    final_k<<<(total4 + 255) / 256, 256>>>(out, y2h, g0_2, b0_2, g2, b2, invN, total4);
}

// round 16
// speedup vs baseline: 4.9273x; 1.3863x over previous
#include <cuda_runtime.h>
#include <cuda_fp16.h>
#include <cstdint>

// ---------------- problem constants ----------------
#define NMAX   200000
#define CCH    64
#define KTAPS  9
#define TN     128          // rows per block (MMA M)
#define NTHR   128
#define LEAK   0.01f
#define EPS_BN 1e-5f
#define WSCALE 256.0f
#define INV_WSCALE (1.0f / 256.0f)

// dynamic smem: 2 stages x 32K (2 taps per stage) / fp32 epilogue tile 34816B
#define TAP_BYTES   16384
#define STAGE_BYTES 32768
#define DSM_BYTES   65536
#define SC_STRIDE 68        // epilogue fp32 tile stride (floats)

// B fragment layout (single plane): per tap = 4q * 2wn * 2p chunks * 32 lanes * 8 halves
#define FRAG_TAP_HALVES   4096
#define FRAG_TENSOR_HALVES (KTAPS * FRAG_TAP_HALVES)   // 36864

// ---------------- scratch (no cudaMalloc allowed) ----------------
// fp16 feature rows: [row][64 fp16]; row nTotal = zero pad
__device__ __half g_fS [((size_t)NMAX + 1) * 64];
__device__ __half g_aSa[((size_t)NMAX + 1) * 64];   // shortcut branch
__device__ __half g_aSb[((size_t)NMAX + 1) * 64];   // main branch
__device__ __half g_y2h[(size_t)NMAX * 64];         // y2 (shortcut output) fp16
__device__ __half g_wFrag[4 * FRAG_TENSOR_HALVES];  // B in per-lane MMA fragment layout
__device__ __half g_biasHi[4 * 64 * 16];            // [tensor][o*16 + tap], x256
__device__ float g_sums [4][CCH];
__device__ float g_sumsq[4][CCH];

// ---------------- helpers ----------------
__device__ __forceinline__ uint32_t smem_u32(const void* p) {
    uint32_t a;
    asm("{ .reg .u64 t; cvta.to.shared.u64 t, %1; cvt.u32.u64 %0, t; }" : "=r"(a) : "l"(p));
    return a;
}
__device__ __forceinline__ void ldsm4(uint32_t* r, uint32_t addr) {
    asm volatile("ldmatrix.sync.aligned.m8n8.x4.shared.b16 {%0,%1,%2,%3}, [%4];"
        : "=r"(r[0]), "=r"(r[1]), "=r"(r[2]), "=r"(r[3]) : "r"(addr));
}
__device__ __forceinline__ void mma16816(float* c, const uint32_t* a, const uint32_t* b) {
    asm volatile("mma.sync.aligned.m16n8k16.row.col.f32.f16.f16.f32 "
        "{%0,%1,%2,%3}, {%4,%5,%6,%7}, {%8,%9}, {%0,%1,%2,%3};"
        : "+f"(c[0]), "+f"(c[1]), "+f"(c[2]), "+f"(c[3])
        : "r"(a[0]), "r"(a[1]), "r"(a[2]), "r"(a[3]), "r"(b[0]), "r"(b[1]));
}
__device__ __forceinline__ uint32_t pack2h(float a, float b) {
    __half2 h = __floats2half2_rn(a, b);
    return *(uint32_t*)&h;
}

// one packed fp16x2 B-frag reg: {W[kk][nn], W[kk+1][nn]} * scale * WSCALE
__device__ __forceinline__ uint32_t frag_reg1(const float* __restrict__ src,
                                              const float* __restrict__ sck,
                                              int kk, int nn) {
    const float s0 = sck ? sck[kk] : 1.f;
    const float s1 = sck ? sck[kk + 1] : 1.f;
    return pack2h(src[kk * 64 + nn] * s0 * WSCALE,
                  src[(kk + 1) * 64 + nn] * s1 * WSCALE);
}

// fragment slots per tap: 512 uint4 = [chunk 0..15][lane 0..31]
// chunk = q*4 + wn*2 + p
__device__ __forceinline__ void write_frags(const float* __restrict__ src,
                                            const float* __restrict__ sck,
                                            __half* __restrict__ dstTap, int tid) {
#pragma unroll
    for (int i = 0; i < 2; ++i) {
        const int idx = tid + i * 256;           // 0..511 uint4 slots
        const int lane = idx & 31;
        const int chunk = idx >> 5;              // 0..15
        const int q = chunk >> 2, wn = (chunk >> 1) & 1, p = chunk & 1;
        const int m = lane & 3, nr = lane >> 2;
        const int k0 = 16 * q;
        const int n0 = wn * 32 + 16 * p + nr;
        uint4 o;
        o.x = frag_reg1(src, sck, k0 + 2 * m,     n0);
        o.y = frag_reg1(src, sck, k0 + 2 * m,     n0 + 8);
        o.z = frag_reg1(src, sck, k0 + 8 + 2 * m, n0);
        o.w = frag_reg1(src, sck, k0 + 8 + 2 * m, n0 + 8);
        ((uint4*)dstTap)[idx] = o;
    }
}

// ---------------- merged preamble: split + prep_plain + zero (one launch) ----------------
__global__ __launch_bounds__(256)
void pre_k(const float* __restrict__ features,
           const float* __restrict__ w1, const float* __restrict__ w2,
           int nTotal, int gridS)
{
    const int bid = blockIdx.x, tid = threadIdx.x;
    if (bid < gridS) {
        const int row = bid * 256 + tid;
        if (row >= nTotal) return;
        const float4* s = (const float4*)(features + (size_t)row * CCH);
        uint4* d = (uint4*)(g_fS + (size_t)row * 64);
#pragma unroll
        for (int g = 0; g < 8; ++g) {
            const float4 v0 = s[2 * g], v1 = s[2 * g + 1];
            uint4 o;
            o.x = pack2h(v0.x, v0.y);
            o.y = pack2h(v0.z, v0.w);
            o.z = pack2h(v1.x, v1.y);
            o.w = pack2h(v1.z, v1.w);
            d[g] = o;
        }
        return;
    }
    const int j = bid - gridS;
    if (j < 2 * KTAPS) {
        const int t = (j < KTAPS) ? 0 : 2;
        const int k = j % KTAPS;
        const float* src = ((t == 0) ? w1 : w2) + k * 4096;
        __half* dst = g_wFrag + (size_t)t * FRAG_TENSOR_HALVES + (size_t)k * FRAG_TAP_HALVES;
        write_frags(src, nullptr, dst, tid);
        return;
    }
    // zero block
    ((float*)g_sums)[tid]  = 0.f;
    ((float*)g_sumsq)[tid] = 0.f;
#pragma unroll
    for (int r = 0; r < 8; ++r)
        ((uint32_t*)g_biasHi)[tid + r * 256] = 0u;
    if (tid < 32) ((uint32_t*)(g_fS + (size_t)nTotal * 64))[tid] = 0u;
    else if (tid < 64) ((uint32_t*)(g_aSa + (size_t)nTotal * 64))[tid - 32] = 0u;
    else if (tid < 96) ((uint32_t*)(g_aSb + (size_t)nTotal * 64))[tid - 64] = 0u;
}

// fold BN(stage) into weights -> fragment layout; bias_k[o] = 256*sum_c shift[c]*W[c,o]
__global__ void prep_fold2_k(const float* __restrict__ wA, const float* __restrict__ wB,
                             const float* __restrict__ gA, const float* __restrict__ bA,
                             const float* __restrict__ gB, const float* __restrict__ bB,
                             float invN) {
    __shared__ float sc[64], sh[64];
    const int sel = blockIdx.x / KTAPS;           // 0 or 1
    const int k = blockIdx.x % KTAPS, tid = threadIdx.x;
    const float* w = sel ? wB : wA;
    const float* gamma = sel ? gB : gA;
    const float* beta  = sel ? bB : bA;
    const int stage = sel ? 2 : 0;
    const int tensor = sel ? 3 : 1;
    if (tid < 64) {
        const float m = g_sums[stage][tid] * invN;
        const float v = g_sumsq[stage][tid] * invN - m * m;
        const float a = gamma[tid] * rsqrtf(v + EPS_BN);
        sc[tid] = a;
        sh[tid] = beta[tid] - m * a;
    }
    __syncthreads();
    const float* src = w + (size_t)k * 4096;
    __half* dst = g_wFrag + (size_t)tensor * FRAG_TENSOR_HALVES + (size_t)k * FRAG_TAP_HALVES;
    write_frags(src, sc, dst, tid);
    if (tid < 64) {
        float s = 0.f;
#pragma unroll 8
        for (int c = 0; c < 64; ++c) s += sh[c] * src[c * 64 + tid];
        g_biasHi[tensor * 1024 + tid * 16 + k] = __float2half_rn(s * WSCALE);
    }
}

// ---------------- main conv kernel (fp16 1-term B; paired taps, 1 sync / 2 taps) ----------------
// outMode: 0 = fp32 rows (dstF), 1/2 = fp16 rows (dstH)
template <bool HAS_BIAS>
__global__ __launch_bounds__(NTHR, 3)
void conv_mma_k(const __half* __restrict__ src0, const __half* __restrict__ src1,
                const int* __restrict__ nbr0, const int* __restrict__ nbr1,
                int wt0, int wt1,
                float* __restrict__ dstF0, float* __restrict__ dstF1,
                __half* __restrict__ dstH0, __half* __restrict__ dstH1,
                int om0, int om1,
                int nTotal, int stage0, int stage1)
{
    extern __shared__ __align__(128) char smemc[];
    __shared__ uint4 sBBh[128];       // bias [64 o][16 taps] fp16
    __shared__ int   sNbr[128 * KTAPS];

    const int sel = blockIdx.y;
    const __half* __restrict__ src = sel ? src1 : src0;
    const int*    __restrict__ nbr = sel ? nbr1 : nbr0;
    const int wtIdx = sel ? wt1 : wt0;
    float*  __restrict__ dstF = sel ? dstF1 : dstF0;
    __half* __restrict__ dstH = sel ? dstH1 : dstH0;
    const int outMode = sel ? om1 : om0;
    const int stage = sel ? stage1 : stage0;

    const int tid   = threadIdx.x;
    const int lane  = tid & 31;
    const int wid   = tid >> 5;
    const int nBase = blockIdx.x * TN;
    const bool rowOK = (nBase + tid) < nTotal;

    const uint32_t sbase = smem_u32(smemc);
    // 2M x 2N warp grid: warp tile = 64 rows x 32 outch
    const int wm = wid & 1, wn = wid >> 1;
    const int rowBase = wm * 64;
    const int colBase = wn * 32;
    const int lsw = lane & 7, l15 = lane & 15, l16 = lane >> 4;

#pragma unroll
    for (int j = 0; j < KTAPS; ++j)
        sNbr[tid * KTAPS + j] = rowOK ? nbr[(size_t)(nBase + tid) * KTAPS + j] : nTotal;

    if (HAS_BIAS)
        sBBh[tid] = ((const uint4*)(g_biasHi + wtIdx * 1024))[tid];

    float C[4][4][4];
#pragma unroll
    for (int mt = 0; mt < 4; ++mt)
#pragma unroll
        for (int nt = 0; nt < 4; ++nt)
#pragma unroll
            for (int i = 0; i < 4; ++i) C[mt][nt][i] = 0.f;

    // B fragments: [tap][chunk = q*4 + wn*2 + p][lane] uint4
    const uint4* bF = (const uint4*)(g_wFrag + (size_t)wtIdx * FRAG_TENSOR_HALVES) + lane;

    // cooperative gather: 8 lanes per row, 4 rows per instruction (full 128B lines)
    const int gRow0  = (wid << 5) + (lane >> 3);
    const int gChunk = lane & 7;
    uint4 pa[8];

    auto tapAddr = [&](int k) -> uint32_t {
        return sbase + (uint32_t)(((k >> 1) & 1) * STAGE_BYTES + (k & 1) * TAP_BYTES);
    };

    auto ldgA = [&](int k) {
#pragma unroll
        for (int it = 0; it < 8; ++it) {
            const int rl = gRow0 + (it << 2);
            const int nidx = sNbr[rl * KTAPS + k];
            pa[it] = *(const uint4*)(src + (size_t)nidx * 64 + (gChunk << 3));
        }
    };
    auto stsA = [&](int k) {
        char* ab = smemc + (tapAddr(k) - sbase);
#pragma unroll
        for (int it = 0; it < 8; ++it) {
            const int rl = gRow0 + (it << 2);
            *(uint4*)(ab + rl * 128 + ((gChunk ^ (rl & 7)) << 4)) = pa[it];
        }
    };
    auto mmaTap = [&](int k) {
        const uint32_t ab = tapAddr(k);
#pragma unroll
        for (int q = 0; q < 4; ++q) {
            const int kg = 2 * q + l16;
            uint32_t a_[4][4];
#pragma unroll
            for (int mt = 0; mt < 4; ++mt) {
                const uint32_t off =
                    (uint32_t)((rowBase + mt * 16 + l15) * 128 + ((kg ^ lsw) << 4));
                ldsm4(a_[mt], ab + off);
            }
            // B fragments direct from gmem (L1-hot, fully coalesced); single plane
            const uint4* bq = bF + (size_t)((k * 4 + q) * 4 + wn * 2) * 32;
            const uint4 f0 = bq[0], f1 = bq[32];
            uint32_t bh[4][2];
            bh[0][0] = f0.x; bh[1][0] = f0.y; bh[0][1] = f0.z; bh[1][1] = f0.w;
            bh[2][0] = f1.x; bh[3][0] = f1.y; bh[2][1] = f1.z; bh[3][1] = f1.w;
#pragma unroll
            for (int mt = 0; mt < 4; ++mt)
#pragma unroll
                for (int nt = 0; nt < 4; ++nt)
                    mma16816(C[mt][nt], a_[mt], bh[nt]);
        }
    };

    __syncthreads();
    ldgA(0); stsA(0);
    ldgA(1); stsA(1);

#pragma unroll
    for (int it = 0; it < 5; ++it) {
        __syncthreads();             // pair (2it,2it+1) visible; other stage free
        const int k0 = 2 * it, k1 = 2 * it + 1;

        if (k0 + 2 < KTAPS) ldgA(k0 + 2);
        mmaTap(k0);
        if (k0 + 2 < KTAPS) stsA(k0 + 2);

        if (k1 < KTAPS) {
            if (k1 + 2 < KTAPS) ldgA(k1 + 2);
            mmaTap(k1);
            if (k1 + 2 < KTAPS) stsA(k1 + 2);
        }
    }

    // ---- bias MMA: C += V(128x16) * B(16x64); V fragments built from sNbr ----
    if (HAS_BIAS) {
        uint32_t av[4][4];
        const int fr = lane >> 2, fc = (lane & 3) * 2;
#pragma unroll
        for (int mt = 0; mt < 4; ++mt) {
            const int r0 = rowBase + mt * 16 + fr;
            const int r1 = r0 + 8;
#pragma unroll
            for (int j = 0; j < 4; ++j) {
                const int rr = (j & 1) ? r1 : r0;
                const int c0 = fc + ((j >> 1) << 3);
                uint32_t lo = 0u, hi = 0u;
                if (c0     < KTAPS && sNbr[rr * KTAPS + c0]     < nTotal) lo = 0x3C00u;
                if (c0 + 1 < KTAPS && sNbr[rr * KTAPS + c0 + 1] < nTotal) hi = 0x3C00u;
                av[mt][j] = lo | (hi << 16);
            }
        }
        const uint32_t bhb = smem_u32(sBBh);
        uint32_t bbh[4][2];
#pragma unroll
        for (int p = 0; p < 2; ++p) {
            const uint32_t off = (uint32_t)((colBase + 16 * p + l15) * 32 + l16 * 16);
            uint32_t r[4];
            ldsm4(r, bhb + off);
            bbh[2*p][0] = r[0]; bbh[2*p+1][0] = r[1];
            bbh[2*p][1] = r[2]; bbh[2*p+1][1] = r[3];
        }
#pragma unroll
        for (int mt = 0; mt < 4; ++mt)
#pragma unroll
            for (int nt = 0; nt < 4; ++nt)
                mma16816(C[mt][nt], av[mt], bbh[nt]);
    }

    // ---- epilogue: descale + leaky -> smem fp32 tile -> store + stats ----
    __syncthreads();
    float* sC = (float*)smemc;                   // [128][SC_STRIDE] = 34816B
    const int fg = lane >> 2, ft2 = (lane & 3) * 2;
#pragma unroll
    for (int mt = 0; mt < 4; ++mt)
#pragma unroll
        for (int nt = 0; nt < 4; ++nt) {
            float* c = C[mt][nt];
#pragma unroll
            for (int i = 0; i < 4; ++i) {
                const float v = c[i] * INV_WSCALE;
                c[i] = (v > 0.f) ? v : LEAK * v;
            }
            const int r0 = rowBase + mt * 16 + fg;
            const int col = colBase + nt * 8 + ft2;
            *(float2*)&sC[r0 * SC_STRIDE + col]       = make_float2(c[0], c[1]);
            *(float2*)&sC[(r0 + 8) * SC_STRIDE + col] = make_float2(c[2], c[3]);
        }
    __syncthreads();

    if (rowOK) {
        const float4* rowp = (const float4*)(sC + tid * SC_STRIDE);
        if (outMode != 0) {          // fp16 rows
            uint4* d = (uint4*)(dstH + (size_t)(nBase + tid) * 64);
#pragma unroll
            for (int g = 0; g < 8; ++g) {
                const float4 v0 = rowp[2 * g], v1 = rowp[2 * g + 1];
                uint4 o;
                o.x = pack2h(v0.x, v0.y);
                o.y = pack2h(v0.z, v0.w);
                o.z = pack2h(v1.x, v1.y);
                o.w = pack2h(v1.z, v1.w);
                d[g] = o;
            }
        } else {                     // fp32 rows
            float4* drow = (float4*)(dstF + (size_t)(nBase + tid) * CCH);
#pragma unroll
            for (int c4 = 0; c4 < 16; ++c4) drow[c4] = rowp[c4];
        }
    }

    {
        const int ch = tid >> 1, half = tid & 1;
        float s = 0.f, s2 = 0.f;
#pragma unroll 8
        for (int i = 0; i < 64; ++i) {
            const float v = sC[(half * 64 + i) * SC_STRIDE + ch];
            s += v; s2 += v * v;
        }
        s  += __shfl_xor_sync(0xffffffffu, s, 1);
        s2 += __shfl_xor_sync(0xffffffffu, s2, 1);
        if (!half) {
            atomicAdd(&g_sums[stage][ch], s);
            atomicAdd(&g_sumsq[stage][ch], s2);
        }
    }
}

// out = BN3(out) + BN1(y2h); coefficients for stages 1,3 computed inline
__global__ __launch_bounds__(256)
void final_k(float* __restrict__ out, const __half* __restrict__ y2h,
             const float* __restrict__ g1_, const float* __restrict__ b1_,
             const float* __restrict__ g3_, const float* __restrict__ b3_,
             float invN, int total4)
{
    __shared__ float c1[64], s1[64], c3[64], s3[64];
    const int tid = threadIdx.x;
    if (tid < 64) {
        const float m1 = g_sums[1][tid] * invN;
        const float v1 = g_sumsq[1][tid] * invN - m1 * m1;
        const float a1 = g1_[tid] * rsqrtf(v1 + EPS_BN);
        c1[tid] = a1; s1[tid] = b1_[tid] - m1 * a1;
        const float m3 = g_sums[3][tid] * invN;
        const float v3 = g_sumsq[3][tid] * invN - m3 * m3;
        const float a3 = g3_[tid] * rsqrtf(v3 + EPS_BN);
        c3[tid] = a3; s3[tid] = b3_[tid] - m3 * a3;
    }
    __syncthreads();
    const int i = blockIdx.x * 256 + tid;
    if (i >= total4) return;
    float4 a = ((float4*)out)[i];
    const uint2 hb = ((const uint2*)y2h)[i];
    const __half2 p0 = *(const __half2*)&hb.x;
    const __half2 p1 = *(const __half2*)&hb.y;
    const float bx = __low2float(p0), by = __high2float(p0);
    const float bz = __low2float(p1), bw = __high2float(p1);
    const int c = (i * 4) & 63;
    a.x = fmaf(a.x, c3[c + 0], s3[c + 0]) + fmaf(bx, c1[c + 0], s1[c + 0]);
    a.y = fmaf(a.y, c3[c + 1], s3[c + 1]) + fmaf(by, c1[c + 1], s1[c + 1]);
    a.z = fmaf(a.z, c3[c + 2], s3[c + 2]) + fmaf(bz, c1[c + 2], s1[c + 2]);
    a.w = fmaf(a.w, c3[c + 3], s3[c + 3]) + fmaf(bw, c1[c + 3], s1[c + 3]);
    ((float4*)out)[i] = a;
}

// ---------------- launcher ----------------
extern "C" void kernel_launch(void* const* d_in, const int* in_sizes, int n_in,
                              void* d_out, int out_size)
{
    const float* features = (const float*)d_in[0];
    const float* w1   = (const float*)d_in[1];
    const float* w1_2 = (const float*)d_in[2];
    const float* w2   = (const float*)d_in[3];
    const float* w3   = (const float*)d_in[4];
    const float* g0   = (const float*)d_in[5];
    const float* b0   = (const float*)d_in[6];
    const float* g0_2 = (const float*)d_in[7];
    const float* b0_2 = (const float*)d_in[8];
    const float* g1   = (const float*)d_in[9];
    const float* b1   = (const float*)d_in[10];
    const float* g2   = (const float*)d_in[11];
    const float* b2   = (const float*)d_in[12];
    const int*   nbr13 = (const int*)d_in[13];
    const int*   nbr31 = (const int*)d_in[14];

    const int nTotal = in_sizes[0] / CCH;
    const float invN = 1.0f / (float)nTotal;
    const int grid   = (nTotal + TN - 1) / TN;
    const int gridS  = (nTotal + 255) / 256;

    cudaFuncSetAttribute(conv_mma_k<false>,
                         cudaFuncAttributeMaxDynamicSharedMemorySize, DSM_BYTES);
    cudaFuncSetAttribute(conv_mma_k<true>,
                         cudaFuncAttributeMaxDynamicSharedMemorySize, DSM_BYTES);

    __half *fS = nullptr, *aSa = nullptr, *aSb = nullptr, *y2h = nullptr;
    cudaGetSymbolAddress((void**)&fS,  g_fS);
    cudaGetSymbolAddress((void**)&aSa, g_aSa);
    cudaGetSymbolAddress((void**)&aSb, g_aSb);
    cudaGetSymbolAddress((void**)&y2h, g_y2h);
    float* out = (float*)d_out;

    // merged preamble: split + weight frags + zeroing (one launch)
    pre_k<<<gridS + 2 * KTAPS + 1, 256>>>(features, w1, w2, nTotal, gridS);

    // phase A: conv0 (nbr13, w1 -> aSa, stats0) || conv2 (nbr31, w2 -> aSb, stats2)
    {
        dim3 g2d(grid, 2);
        conv_mma_k<false><<<g2d, NTHR, DSM_BYTES>>>(
            fS, fS, nbr13, nbr31, 0, 2,
            nullptr, nullptr, aSa, aSb, 1, 1, nTotal, 0, 2);
    }

    // fold BN0 into w1_2 (tensor1) and BN2 into w3 (tensor3), one launch
    prep_fold2_k<<<2 * KTAPS, 256>>>(w1_2, w3, g0, b0, g1, b1, invN);

    // phase B: conv1 (aSa, nbr31, w1_2 -> y2h fp16, stats1)
    //        || conv3 (aSb, nbr13, w3 -> out fp32, stats3)
    {
        dim3 g2d(grid, 2);
        conv_mma_k<true><<<g2d, NTHR, DSM_BYTES>>>(
            aSa, aSb, nbr31, nbr13, 1, 3,
            nullptr, out, y2h, nullptr, 2, 0, nTotal, 1, 3);
    }

    // out = BN3(out) + BN1(y2h)
    const int total4 = nTotal * CCH / 4;
    final_k<<<(total4 + 255) / 256, 256>>>(out, y2h, g0_2, b0_2, g2, b2, invN, total4);
}